// round 1
// baseline (speedup 1.0000x reference)
#include <cuda_runtime.h>
#include <math.h>

// Problem constants (fixed by the dataset)
#define BD   8
#define TD   2048
#define DD   512
#define PD   8
#define NTOT (BD * TD)   // 16384

// ---------------------------------------------------------------------------
// Scratch (device globals — no allocations allowed)
// ---------------------------------------------------------------------------
__device__ float g_s[(size_t)DD * NTOT];      // s values, i-major: s[i*N + n]
__device__ float g_zl[(size_t)NTOT * DD];     // z logits
__device__ float g_hbar[(size_t)NTOT * DD];   // h_bar

// ---------------------------------------------------------------------------
// build_s: for each (n, i) compute s = k + t where
//   k = clamp(#(p[i,j] < x) - 1, 0, 6), t = clamp((x-p[k])/(p[k+1]-p[k]),0,1)
// Input X is (N, 512) n-major; output S is (512, N) i-major (transposed so the
// GEMM's A-column loads are coalesced).
// ---------------------------------------------------------------------------
__global__ __launch_bounds__(256) void build_s_kernel(
    const float* __restrict__ X, const float* __restrict__ Pp,
    float* __restrict__ S, int N) {
    __shared__ float tile[32][33];
    int i0 = blockIdx.x * 32;
    int n0 = blockIdx.y * 32;
    int tx = threadIdx.x;   // over i
    int ty = threadIdx.y;   // 0..7
    int i = i0 + tx;

    float p[8];
#pragma unroll
    for (int j = 0; j < 8; ++j) p[j] = Pp[i * 8 + j];

#pragma unroll
    for (int r = 0; r < 4; ++r) {
        int nl = ty + 8 * r;
        int n = n0 + nl;
        float x = X[(size_t)n * DD + i];
        // find segment: k = largest j in [0,6] with p[j] < x (else 0)
        int k = 0;
        float pl = p[0], pr = p[1];
#pragma unroll
        for (int j = 1; j <= 6; ++j) {
            if (p[j] < x) { k = j; pl = p[j]; pr = p[j + 1]; }
        }
        float t = (x - pl) / (pr - pl);
        t = fminf(fmaxf(t, 0.0f), 1.0f);
        tile[nl][tx] = (float)k + t;
    }
    __syncthreads();
#pragma unroll
    for (int r = 0; r < 4; ++r) {
        int il = ty + 8 * r;
        S[(size_t)(i0 + il) * N + n0 + tx] = tile[tx][il];
    }
}

// ---------------------------------------------------------------------------
// APL GEMM: out(N,512) = C(N,4096) @ V(4096,512)
//   C[n, i*8+p] = max(0, 1 - |s[n,i] - p|)  built on the fly in SMEM.
// Block tile 128(M) x 128(N), 256 threads, 8x8 micro-tile, K step = one i (8).
// ---------------------------------------------------------------------------
__global__ __launch_bounds__(256) void apl_gemm_kernel(
    const float* __restrict__ S, const float* __restrict__ V,
    float* __restrict__ out, int N) {
    __shared__ float As[8][128];
    __shared__ float Bs[8][128];
    float* Bsf = &Bs[0][0];

    const int bm = blockIdx.x * 128;
    const int bn = blockIdx.y * 128;
    const int tid = threadIdx.x;
    const int tx = tid & 15;    // over output cols
    const int ty = tid >> 4;    // over output rows

    float acc[8][8];
#pragma unroll
    for (int r = 0; r < 8; ++r)
#pragma unroll
        for (int c = 0; c < 8; ++c) acc[r][c] = 0.0f;

    // prefetch registers for i=0
    float sv = 0.0f;
    float bv[4];
    {
        if (tid < 128) sv = S[(size_t)0 * N + bm + tid];
#pragma unroll
        for (int r = 0; r < 4; ++r) {
            int e = tid + 256 * r;
            int pp = e >> 7, oo = e & 127;
            bv[r] = V[((size_t)0 * 8 + pp) * 512 + bn + oo];
        }
    }

    for (int i = 0; i < 512; ++i) {
        __syncthreads();   // previous compute done, smem free
        if (tid < 128) {
#pragma unroll
            for (int pp = 0; pp < 8; ++pp)
                As[pp][tid] = fmaxf(0.0f, 1.0f - fabsf(sv - (float)pp));
        }
#pragma unroll
        for (int r = 0; r < 4; ++r) Bsf[tid + 256 * r] = bv[r];
        __syncthreads();

        // prefetch next i while computing
        float sv2 = 0.0f;
        float bv2[4] = {0.f, 0.f, 0.f, 0.f};
        if (i < 511) {
            int in = i + 1;
            if (tid < 128) sv2 = S[(size_t)in * N + bm + tid];
#pragma unroll
            for (int r = 0; r < 4; ++r) {
                int e = tid + 256 * r;
                int pp = e >> 7, oo = e & 127;
                bv2[r] = V[((size_t)in * 8 + pp) * 512 + bn + oo];
            }
        }

#pragma unroll
        for (int pp = 0; pp < 8; ++pp) {
            float a[8], b[8];
#pragma unroll
            for (int r = 0; r < 8; ++r) a[r] = As[pp][ty * 8 + r];
#pragma unroll
            for (int c = 0; c < 8; ++c) b[c] = Bs[pp][tx * 8 + c];
#pragma unroll
            for (int r = 0; r < 8; ++r)
#pragma unroll
                for (int c = 0; c < 8; ++c)
                    acc[r][c] = fmaf(a[r], b[c], acc[r][c]);
        }

        sv = sv2;
#pragma unroll
        for (int r = 0; r < 4; ++r) bv[r] = bv2[r];
    }

#pragma unroll
    for (int r = 0; r < 8; ++r) {
        int row = bm + ty * 8 + r;
        float4* o4 = (float4*)&out[(size_t)row * 512 + bn + tx * 8];
        o4[0] = make_float4(acc[r][0], acc[r][1], acc[r][2], acc[r][3]);
        o4[1] = make_float4(acc[r][4], acc[r][5], acc[r][6], acc[r][7]);
    }
}

// ---------------------------------------------------------------------------
// Sequential scan: h[t] = (1-z) h[t-1] + z h_bar, z = sigmoid(zl), h0 = 0.
// One thread per (b, d) channel.
// ---------------------------------------------------------------------------
__global__ __launch_bounds__(256) void scan_kernel(
    const float* __restrict__ zl, const float* __restrict__ hb,
    float* __restrict__ h) {
    int c = blockIdx.x * blockDim.x + threadIdx.x;  // 0..4095
    if (c >= BD * DD) return;
    int b = c >> 9;
    int d = c & 511;
    size_t base = (size_t)b * TD * DD + d;
    float hc = 0.0f;
#pragma unroll 8
    for (int t = 0; t < TD; ++t) {
        size_t idx = base + (size_t)t * DD;
        float zv = 1.0f / (1.0f + expf(-zl[idx]));
        float hbv = hb[idx];
        hc = fmaf(zv, hbv - hc, hc);
        h[idx] = hc;
    }
}

// ---------------------------------------------------------------------------
// Max-abs norm, in place: row /= (max|row| + 1e-6). One warp per row of 512.
// ---------------------------------------------------------------------------
__global__ __launch_bounds__(256) void norm_kernel(float* __restrict__ h, int rows) {
    int warp = (blockIdx.x * blockDim.x + threadIdx.x) >> 5;
    int lane = threadIdx.x & 31;
    if (warp >= rows) return;
    float4* row = (float4*)(h + (size_t)warp * DD);
    float4 vals[4];
    float m = 0.0f;
#pragma unroll
    for (int j = 0; j < 4; ++j) {
        vals[j] = row[lane + 32 * j];
        m = fmaxf(m, fmaxf(fmaxf(fabsf(vals[j].x), fabsf(vals[j].y)),
                           fmaxf(fabsf(vals[j].z), fabsf(vals[j].w))));
    }
#pragma unroll
    for (int off = 16; off; off >>= 1)
        m = fmaxf(m, __shfl_xor_sync(0xffffffffu, m, off));
    float inv = 1.0f / (m + 1e-6f);
#pragma unroll
    for (int j = 0; j < 4; ++j) {
        vals[j].x *= inv; vals[j].y *= inv; vals[j].z *= inv; vals[j].w *= inv;
        row[lane + 32 * j] = vals[j];
    }
}

// ---------------------------------------------------------------------------
// kernel_launch
// Inputs (metadata order): x, pz0, vz0, ph0, vh0, pz1, vz1, ph1, vh1, po, vo
// Output: [out | h1 | h2], each (B,T,D) fp32.
// ---------------------------------------------------------------------------
extern "C" void kernel_launch(void* const* d_in, const int* in_sizes, int n_in,
                              void* d_out, int out_size) {
    const float* x   = (const float*)d_in[0];
    const float* pz0 = (const float*)d_in[1];
    const float* vz0 = (const float*)d_in[2];
    const float* ph0 = (const float*)d_in[3];
    const float* vh0 = (const float*)d_in[4];
    const float* pz1 = (const float*)d_in[5];
    const float* vz1 = (const float*)d_in[6];
    const float* ph1 = (const float*)d_in[7];
    const float* vh1 = (const float*)d_in[8];
    const float* po  = (const float*)d_in[9];
    const float* vo  = (const float*)d_in[10];

    const int N = in_sizes[0] / DD;  // 16384

    float *s, *zl, *hb;
    cudaGetSymbolAddress((void**)&s,  g_s);
    cudaGetSymbolAddress((void**)&zl, g_zl);
    cudaGetSymbolAddress((void**)&hb, g_hbar);

    float* out = (float*)d_out;
    float* h1  = out + (size_t)N * DD;
    float* h2  = h1 + (size_t)N * DD;

    dim3 tgrid(DD / 32, N / 32);
    dim3 tblk(32, 8);
    dim3 ggrid(N / 128, DD / 128);
    const int gthreads = 256;
    const int scan_blocks = (BD * DD + 255) / 256;
    const int norm_blocks = (N * 32 + 255) / 256;  // one warp per row

    // ---- layer 0 (input x) ----
    build_s_kernel<<<tgrid, tblk>>>(x, pz0, s, N);
    apl_gemm_kernel<<<ggrid, gthreads>>>(s, vz0, zl, N);
    build_s_kernel<<<tgrid, tblk>>>(x, ph0, s, N);
    apl_gemm_kernel<<<ggrid, gthreads>>>(s, vh0, hb, N);
    scan_kernel<<<scan_blocks, 256>>>(zl, hb, h1);
    norm_kernel<<<norm_blocks, 256>>>(h1, N);

    // ---- layer 1 (input h1) ----
    build_s_kernel<<<tgrid, tblk>>>(h1, pz1, s, N);
    apl_gemm_kernel<<<ggrid, gthreads>>>(s, vz1, zl, N);
    build_s_kernel<<<tgrid, tblk>>>(h1, ph1, s, N);
    apl_gemm_kernel<<<ggrid, gthreads>>>(s, vh1, hb, N);
    scan_kernel<<<scan_blocks, 256>>>(zl, hb, h2);
    norm_kernel<<<norm_blocks, 256>>>(h2, N);

    // ---- output APL ----
    build_s_kernel<<<tgrid, tblk>>>(h2, po, s, N);
    apl_gemm_kernel<<<ggrid, gthreads>>>(s, vo, out, N);
}

// round 4
// speedup vs baseline: 1.5876x; 1.5876x over previous
#include <cuda_runtime.h>
#include <cuda_bf16.h>
#include <math.h>
#include <stdint.h>

// Problem constants
#define BD   8
#define TD   2048
#define DD   512
#define NTOT (BD * TD)     // 16384
#define KTOT 4096          // D * P
#define NCHUNK 192         // 3 passes x 64 K-chunks of 64

// ---------------------------------------------------------------------------
// Scratch (device globals — no allocations allowed)
// ---------------------------------------------------------------------------
__device__ float g_s[(size_t)DD * NTOT];        // s values, i-major
__device__ float g_zl[(size_t)NTOT * DD];       // z logits
__device__ float g_hbar[(size_t)NTOT * DD];     // h_bar
__device__ __nv_bfloat16 g_vthi[5][(size_t)DD * KTOT];  // V^T hi split (512 x 4096)
__device__ __nv_bfloat16 g_vtlo[5][(size_t)DD * KTOT];  // V^T lo split

// ---------------------------------------------------------------------------
// helpers
// ---------------------------------------------------------------------------
__device__ __forceinline__ uint32_t smem_u32(const void* p) {
    uint32_t a;
    asm("{ .reg .u64 t; cvta.to.shared.u64 t, %1; cvt.u32.u64 %0, t; }"
        : "=r"(a) : "l"(p));
    return a;
}

#define SWZ(x) ((x) ^ (((x) >> 3) & 0x70))

// ---------------------------------------------------------------------------
// build_s: s[i*N+n] = k + t  (searchsorted + clamped lerp parameter)
// ---------------------------------------------------------------------------
__global__ __launch_bounds__(256) void build_s_kernel(
    const float* __restrict__ X, const float* __restrict__ Pp,
    float* __restrict__ S, int N) {
    __shared__ float tile[32][33];
    int i0 = blockIdx.x * 32;
    int n0 = blockIdx.y * 32;
    int tx = threadIdx.x;
    int ty = threadIdx.y;
    int i = i0 + tx;

    float p[8];
#pragma unroll
    for (int j = 0; j < 8; ++j) p[j] = Pp[i * 8 + j];

#pragma unroll
    for (int r = 0; r < 4; ++r) {
        int nl = ty + 8 * r;
        int n = n0 + nl;
        float x = X[(size_t)n * DD + i];
        int k = 0;
        float pl = p[0], pr = p[1];
#pragma unroll
        for (int j = 1; j <= 6; ++j) {
            if (p[j] < x) { k = j; pl = p[j]; pr = p[j + 1]; }
        }
        float t = (x - pl) / (pr - pl);
        t = fminf(fmaxf(t, 0.0f), 1.0f);
        tile[nl][tx] = (float)k + t;
    }
    __syncthreads();
#pragma unroll
    for (int r = 0; r < 4; ++r) {
        int il = ty + 8 * r;
        S[(size_t)(i0 + il) * N + n0 + tx] = tile[tx][il];
    }
}

// ---------------------------------------------------------------------------
// split_transpose: v (4096 x 512 f32) -> Vt_hi/Vt_lo (512 x 4096 bf16)
// ---------------------------------------------------------------------------
__global__ __launch_bounds__(256) void split_transpose_kernel(
    const float* __restrict__ v, __nv_bfloat16* __restrict__ hi,
    __nv_bfloat16* __restrict__ lo) {
    __shared__ float t[32][33];
    int k0 = blockIdx.x * 32;
    int o0 = blockIdx.y * 32;
    int tx = threadIdx.x, ty = threadIdx.y;
#pragma unroll
    for (int r = 0; r < 4; ++r)
        t[ty + 8 * r][tx] = v[(size_t)(k0 + ty + 8 * r) * DD + o0 + tx];
    __syncthreads();
#pragma unroll
    for (int r = 0; r < 4; ++r) {
        float val = t[tx][ty + 8 * r];
        __nv_bfloat16 h = __float2bfloat16_rn(val);
        float res = val - __bfloat162float(h);
        size_t idx = (size_t)(o0 + ty + 8 * r) * KTOT + k0 + tx;
        hi[idx] = h;
        lo[idx] = __float2bfloat16_rn(res);
    }
}

// ---------------------------------------------------------------------------
// APL HMMA GEMM: out(16384x512) = C(16384x4096)@V(4096x512) in 3 bf16 passes.
// Portable sm_80-class path: cp.async + ldmatrix + mma.sync m16n8k16 bf16.
// SMEM: A ring 2 x 16KB (built on the fly), B ring 3 x 16KB (cp.async).
// ---------------------------------------------------------------------------
#define SMEM_REQ (1024 + 2 * 16384 + 3 * 16384)

__device__ __forceinline__ void load_B_chunk(const __nv_bfloat16* src, int kc,
                                             uint32_t dstb, int tid) {
    const char* g = (const char*)src + (size_t)kc * 128;  // 64 bf16 = 128B
#pragma unroll
    for (int q = 0; q < 4; ++q) {
        int idx = tid + 256 * q;
        int row = idx >> 3, seg = idx & 7;
        uint32_t dst = dstb + SWZ((uint32_t)(row * 128 + seg * 16));
        const void* sp = g + (size_t)row * 8192 + seg * 16;
        asm volatile("cp.async.cg.shared.global [%0], [%1], 16;"
                     :: "r"(dst), "l"(sp) : "memory");
    }
    asm volatile("cp.async.commit_group;" ::: "memory");
}

__device__ __forceinline__ void build_A_chunk(const float* __restrict__ S, int bm,
                                              int kc, int lo, uint32_t ab, int tid) {
#pragma unroll
    for (int q = 0; q < 4; ++q) {
        int idx = tid + 256 * q;
        int n = idx & 127;
        int il = idx >> 7;
        float sv = __ldg(&S[(size_t)(kc * 8 + il) * NTOT + bm + n]);
        uint32_t w[4];
#pragma unroll
        for (int pp = 0; pp < 4; ++pp) {
            float c0 = fmaxf(0.f, 1.f - fabsf(sv - (float)(2 * pp)));
            float c1 = fmaxf(0.f, 1.f - fabsf(sv - (float)(2 * pp + 1)));
            __nv_bfloat16 h0 = __float2bfloat16_rn(c0);
            __nv_bfloat16 h1 = __float2bfloat16_rn(c1);
            if (lo) {
                h0 = __float2bfloat16_rn(c0 - __bfloat162float(h0));
                h1 = __float2bfloat16_rn(c1 - __bfloat162float(h1));
            }
            w[pp] = (uint32_t)__bfloat16_as_ushort(h0) |
                    ((uint32_t)__bfloat16_as_ushort(h1) << 16);
        }
        uint32_t dst = ab + SWZ((uint32_t)(n * 128 + il * 16));
        asm volatile("st.shared.v4.b32 [%0], {%1,%2,%3,%4};"
                     :: "r"(dst), "r"(w[0]), "r"(w[1]), "r"(w[2]), "r"(w[3])
                     : "memory");
    }
}

__device__ __forceinline__ void ldsm4(uint32_t a, uint32_t& r0, uint32_t& r1,
                                      uint32_t& r2, uint32_t& r3) {
    asm volatile("ldmatrix.sync.aligned.m8n8.x4.shared.b16 {%0,%1,%2,%3}, [%4];"
                 : "=r"(r0), "=r"(r1), "=r"(r2), "=r"(r3) : "r"(a));
}

__device__ __forceinline__ void mma16816(float* d, const uint32_t* a,
                                         const uint32_t* b) {
    asm volatile(
        "mma.sync.aligned.m16n8k16.row.col.f32.bf16.bf16.f32 "
        "{%0,%1,%2,%3}, {%4,%5,%6,%7}, {%8,%9}, {%0,%1,%2,%3};"
        : "+f"(d[0]), "+f"(d[1]), "+f"(d[2]), "+f"(d[3])
        : "r"(a[0]), "r"(a[1]), "r"(a[2]), "r"(a[3]), "r"(b[0]), "r"(b[1]));
}

__global__ void __launch_bounds__(256, 2) apl_hmma_kernel(
    const float* __restrict__ S, const __nv_bfloat16* __restrict__ Vhi,
    const __nv_bfloat16* __restrict__ Vlo, float* __restrict__ out) {
    extern __shared__ char smem[];
    uint32_t sb = (smem_u32(smem) + 1023u) & ~1023u;
    const uint32_t Ab = sb;             // 2 x 16KB
    const uint32_t Bb = sb + 32768;     // 3 x 16KB
    const int tid = threadIdx.x;
    const int lane = tid & 31;
    const int wid = tid >> 5;
    const int wm = wid & 1;             // 2 warp rows (64 each)
    const int wn = wid >> 1;            // 4 warp cols (32 each)
    const int bm = blockIdx.x * 128;
    const int bn = blockIdx.y * 128;

    // *** R4 fix: offset B source by this CTA's output-column block ***
    const __nv_bfloat16* VhiB = Vhi + (size_t)bn * KTOT;
    const __nv_bfloat16* VloB = Vlo + (size_t)bn * KTOT;

    float acc[4][4][4];
#pragma unroll
    for (int mi = 0; mi < 4; ++mi)
#pragma unroll
        for (int nj = 0; nj < 4; ++nj)
#pragma unroll
            for (int u = 0; u < 4; ++u) acc[mi][nj][u] = 0.0f;

    // per-thread ldmatrix base offsets (before swizzle / k-step add)
    uint32_t a_off[4], b_off[2];
#pragma unroll
    for (int mi = 0; mi < 4; ++mi) {
        int row = wm * 64 + mi * 16 + (lane & 15);
        a_off[mi] = (uint32_t)(row * 128 + (lane >> 4) * 16);
    }
#pragma unroll
    for (int ni = 0; ni < 2; ++ni) {
        int row = wn * 32 + ni * 16 + (lane & 7) + ((lane & 16) >> 1);
        b_off[ni] = (uint32_t)(row * 128 + ((lane >> 3) & 1) * 16);
    }

    // prologue: B0, B1 in flight; A0 built
    load_B_chunk(VhiB, 0, Bb, tid);
    load_B_chunk(VhiB, 1, Bb + 16384, tid);
    build_A_chunk(S, bm, 0, 0, Ab, tid);

    for (int c = 0; c < NCHUNK; ++c) {
        asm volatile("cp.async.wait_group 1;" ::: "memory");
        __syncthreads();   // B_c arrived; A_c built; old buffers free

        // issue B_{c+2}
        int c2 = c + 2;
        if (c2 < NCHUNK) {
            int p2 = c2 >> 6, k2 = c2 & 63;
            load_B_chunk(p2 == 1 ? VloB : VhiB, k2, Bb + (c2 % 3) * 16384, tid);
        } else {
            asm volatile("cp.async.commit_group;" ::: "memory");
        }

        const uint32_t Acur = Ab + (c & 1) * 16384;
        const uint32_t Bcur = Bb + (c % 3) * 16384;

#pragma unroll
        for (int kk = 0; kk < 4; ++kk) {
            uint32_t af[4][4], bf[4][2];
#pragma unroll
            for (int mi = 0; mi < 4; ++mi)
                ldsm4(Acur + SWZ(a_off[mi] + kk * 32),
                      af[mi][0], af[mi][1], af[mi][2], af[mi][3]);
#pragma unroll
            for (int ni = 0; ni < 2; ++ni) {
                uint32_t r0, r1, r2, r3;
                ldsm4(Bcur + SWZ(b_off[ni] + kk * 32), r0, r1, r2, r3);
                bf[2 * ni][0] = r0; bf[2 * ni][1] = r1;
                bf[2 * ni + 1][0] = r2; bf[2 * ni + 1][1] = r3;
            }
#pragma unroll
            for (int mi = 0; mi < 4; ++mi)
#pragma unroll
                for (int nj = 0; nj < 4; ++nj)
                    mma16816(acc[mi][nj], af[mi], bf[nj]);
        }

        // build A_{c+1} into the other A buffer (overlaps with HMMA drain)
        int c1 = c + 1;
        if (c1 < NCHUNK)
            build_A_chunk(S, bm, c1 & 63, (c1 >> 6) == 2 ? 1 : 0,
                          Ab + (c1 & 1) * 16384, tid);
    }

    // epilogue: direct f32 stores (c0,c1 are adjacent columns -> float2)
#pragma unroll
    for (int mi = 0; mi < 4; ++mi) {
#pragma unroll
        for (int nj = 0; nj < 4; ++nj) {
            int row = bm + wm * 64 + mi * 16 + (lane >> 2);
            int col = bn + wn * 32 + nj * 8 + 2 * (lane & 3);
            float2* p0 = (float2*)&out[(size_t)row * DD + col];
            float2* p1 = (float2*)&out[(size_t)(row + 8) * DD + col];
            *p0 = make_float2(acc[mi][nj][0], acc[mi][nj][1]);
            *p1 = make_float2(acc[mi][nj][2], acc[mi][nj][3]);
        }
    }
}

// ---------------------------------------------------------------------------
// Scan: h[t] = (1-z) h[t-1] + z h_bar, z = sigmoid(zl)
// ---------------------------------------------------------------------------
__global__ __launch_bounds__(256) void scan_kernel(
    const float* __restrict__ zl, const float* __restrict__ hb,
    float* __restrict__ h) {
    int c = blockIdx.x * blockDim.x + threadIdx.x;
    if (c >= BD * DD) return;
    int b = c >> 9;
    int d = c & 511;
    size_t base = (size_t)b * TD * DD + d;
    float hc = 0.0f;
#pragma unroll 8
    for (int t = 0; t < TD; ++t) {
        size_t idx = base + (size_t)t * DD;
        float zv = 1.0f / (1.0f + expf(-zl[idx]));
        float hbv = hb[idx];
        hc = fmaf(zv, hbv - hc, hc);
        h[idx] = hc;
    }
}

// ---------------------------------------------------------------------------
// Max-abs norm, in place
// ---------------------------------------------------------------------------
__global__ __launch_bounds__(256) void norm_kernel(float* __restrict__ h, int rows) {
    int warp = (blockIdx.x * blockDim.x + threadIdx.x) >> 5;
    int lane = threadIdx.x & 31;
    if (warp >= rows) return;
    float4* row = (float4*)(h + (size_t)warp * DD);
    float4 vals[4];
    float m = 0.0f;
#pragma unroll
    for (int j = 0; j < 4; ++j) {
        vals[j] = row[lane + 32 * j];
        m = fmaxf(m, fmaxf(fmaxf(fabsf(vals[j].x), fabsf(vals[j].y)),
                           fmaxf(fabsf(vals[j].z), fabsf(vals[j].w))));
    }
#pragma unroll
    for (int off = 16; off; off >>= 1)
        m = fmaxf(m, __shfl_xor_sync(0xffffffffu, m, off));
    float inv = 1.0f / (m + 1e-6f);
#pragma unroll
    for (int j = 0; j < 4; ++j) {
        vals[j].x *= inv; vals[j].y *= inv; vals[j].z *= inv; vals[j].w *= inv;
        row[lane + 32 * j] = vals[j];
    }
}

// ---------------------------------------------------------------------------
// kernel_launch
// ---------------------------------------------------------------------------
extern "C" void kernel_launch(void* const* d_in, const int* in_sizes, int n_in,
                              void* d_out, int out_size) {
    const float* x   = (const float*)d_in[0];
    const float* pz0 = (const float*)d_in[1];
    const float* vz0 = (const float*)d_in[2];
    const float* ph0 = (const float*)d_in[3];
    const float* vh0 = (const float*)d_in[4];
    const float* pz1 = (const float*)d_in[5];
    const float* vz1 = (const float*)d_in[6];
    const float* ph1 = (const float*)d_in[7];
    const float* vh1 = (const float*)d_in[8];
    const float* po  = (const float*)d_in[9];
    const float* vo  = (const float*)d_in[10];

    const int N = in_sizes[0] / DD;  // 16384

    float *s, *zl, *hb;
    __nv_bfloat16 *vthi, *vtlo;
    cudaGetSymbolAddress((void**)&s,  g_s);
    cudaGetSymbolAddress((void**)&zl, g_zl);
    cudaGetSymbolAddress((void**)&hb, g_hbar);
    cudaGetSymbolAddress((void**)&vthi, g_vthi);
    cudaGetSymbolAddress((void**)&vtlo, g_vtlo);

    static int smem_set = 0;
    if (!smem_set) {
        cudaFuncSetAttribute(apl_hmma_kernel,
                             cudaFuncAttributeMaxDynamicSharedMemorySize, SMEM_REQ);
        smem_set = 1;
    }

    float* out = (float*)d_out;
    float* h1  = out + (size_t)N * DD;
    float* h2  = h1 + (size_t)N * DD;

    dim3 tgrid(DD / 32, N / 32);
    dim3 tblk(32, 8);
    dim3 spgrid(KTOT / 32, DD / 32);
    dim3 ggrid(N / 128, DD / 128);
    const int scan_blocks = (BD * DD + 255) / 256;
    const int norm_blocks = (N * 32 + 255) / 256;
    const size_t VSZ = (size_t)DD * KTOT;

    // precompute V^T hi/lo splits
    const float* vs[5] = {vz0, vh0, vz1, vh1, vo};
    for (int i = 0; i < 5; ++i)
        split_transpose_kernel<<<spgrid, tblk>>>(vs[i], vthi + i * VSZ, vtlo + i * VSZ);

    // ---- layer 0 ----
    build_s_kernel<<<tgrid, tblk>>>(x, pz0, s, N);
    apl_hmma_kernel<<<ggrid, 256, SMEM_REQ>>>(s, vthi + 0 * VSZ, vtlo + 0 * VSZ, zl);
    build_s_kernel<<<tgrid, tblk>>>(x, ph0, s, N);
    apl_hmma_kernel<<<ggrid, 256, SMEM_REQ>>>(s, vthi + 1 * VSZ, vtlo + 1 * VSZ, hb);
    scan_kernel<<<scan_blocks, 256>>>(zl, hb, h1);
    norm_kernel<<<norm_blocks, 256>>>(h1, N);

    // ---- layer 1 ----
    build_s_kernel<<<tgrid, tblk>>>(h1, pz1, s, N);
    apl_hmma_kernel<<<ggrid, 256, SMEM_REQ>>>(s, vthi + 2 * VSZ, vtlo + 2 * VSZ, zl);
    build_s_kernel<<<tgrid, tblk>>>(h1, ph1, s, N);
    apl_hmma_kernel<<<ggrid, 256, SMEM_REQ>>>(s, vthi + 3 * VSZ, vtlo + 3 * VSZ, hb);
    scan_kernel<<<scan_blocks, 256>>>(zl, hb, h2);
    norm_kernel<<<norm_blocks, 256>>>(h2, N);

    // ---- output APL ----
    build_s_kernel<<<tgrid, tblk>>>(h2, po, s, N);
    apl_hmma_kernel<<<ggrid, 256, SMEM_REQ>>>(s, vthi + 4 * VSZ, vtlo + 4 * VSZ, out);
}

// round 5
// speedup vs baseline: 1.8761x; 1.1817x over previous
#include <cuda_runtime.h>
#include <cuda_bf16.h>
#include <math.h>
#include <stdint.h>

// Problem constants
#define BD   8
#define TD   2048
#define DD   512
#define NTOT (BD * TD)     // 16384
#define KTOT 4096          // D * P
#define NKC  64            // K-chunks of 64 elements

// ---------------------------------------------------------------------------
// Scratch (device globals — no allocations allowed)
// ---------------------------------------------------------------------------
__device__ float g_s[(size_t)DD * NTOT];        // s values, i-major
__device__ float g_zl[(size_t)NTOT * DD];       // z logits
__device__ float g_hbar[(size_t)NTOT * DD];     // h_bar
__device__ __nv_bfloat16 g_vthi[5][(size_t)DD * KTOT];  // V^T hi split (512 x 4096)
__device__ __nv_bfloat16 g_vtlo[5][(size_t)DD * KTOT];  // V^T lo split

// ---------------------------------------------------------------------------
// helpers
// ---------------------------------------------------------------------------
__device__ __forceinline__ uint32_t smem_u32(const void* p) {
    uint32_t a;
    asm("{ .reg .u64 t; cvta.to.shared.u64 t, %1; cvt.u32.u64 %0, t; }"
        : "=r"(a) : "l"(p));
    return a;
}

#define SWZ(x) ((x) ^ (((x) >> 3) & 0x70))

// ---------------------------------------------------------------------------
// build_s: s[i*N+n] = k + t  (searchsorted + clamped lerp parameter)
// ---------------------------------------------------------------------------
__global__ __launch_bounds__(256) void build_s_kernel(
    const float* __restrict__ X, const float* __restrict__ Pp,
    float* __restrict__ S, int N) {
    __shared__ float tile[32][33];
    int i0 = blockIdx.x * 32;
    int n0 = blockIdx.y * 32;
    int tx = threadIdx.x;
    int ty = threadIdx.y;
    int i = i0 + tx;

    float p[8];
#pragma unroll
    for (int j = 0; j < 8; ++j) p[j] = Pp[i * 8 + j];

#pragma unroll
    for (int r = 0; r < 4; ++r) {
        int nl = ty + 8 * r;
        int n = n0 + nl;
        float x = X[(size_t)n * DD + i];
        int k = 0;
        float pl = p[0], pr = p[1];
#pragma unroll
        for (int j = 1; j <= 6; ++j) {
            if (p[j] < x) { k = j; pl = p[j]; pr = p[j + 1]; }
        }
        float t = (x - pl) / (pr - pl);
        t = fminf(fmaxf(t, 0.0f), 1.0f);
        tile[nl][tx] = (float)k + t;
    }
    __syncthreads();
#pragma unroll
    for (int r = 0; r < 4; ++r) {
        int il = ty + 8 * r;
        S[(size_t)(i0 + il) * N + n0 + tx] = tile[tx][il];
    }
}

// ---------------------------------------------------------------------------
// split_transpose: v (4096 x 512 f32) -> Vt_hi/Vt_lo (512 x 4096 bf16)
// ---------------------------------------------------------------------------
__global__ __launch_bounds__(256) void split_transpose_kernel(
    const float* __restrict__ v, __nv_bfloat16* __restrict__ hi,
    __nv_bfloat16* __restrict__ lo) {
    __shared__ float t[32][33];
    int k0 = blockIdx.x * 32;
    int o0 = blockIdx.y * 32;
    int tx = threadIdx.x, ty = threadIdx.y;
#pragma unroll
    for (int r = 0; r < 4; ++r)
        t[ty + 8 * r][tx] = v[(size_t)(k0 + ty + 8 * r) * DD + o0 + tx];
    __syncthreads();
#pragma unroll
    for (int r = 0; r < 4; ++r) {
        float val = t[tx][ty + 8 * r];
        __nv_bfloat16 h = __float2bfloat16_rn(val);
        float res = val - __bfloat162float(h);
        size_t idx = (size_t)(o0 + ty + 8 * r) * KTOT + k0 + tx;
        hi[idx] = h;
        lo[idx] = __float2bfloat16_rn(res);
    }
}

// ---------------------------------------------------------------------------
// APL HMMA GEMM, fused 3-term split per K-chunk.
// 512 threads, 16 warps (4x4), warp tile 32x32, CTA tile 128(M)x128(N).
// SMEM: A_hi[2],A_lo[2] (built on the fly), B_hi[3],B_lo[3] (cp.async ring).
// ---------------------------------------------------------------------------
#define TILE16K 16384
#define SMEM_REQ (1024 + 4 * TILE16K + 6 * TILE16K)

__device__ __forceinline__ void load_B_pair(const __nv_bfloat16* hi,
                                            const __nv_bfloat16* lo, int kc,
                                            uint32_t dsth, uint32_t dstl, int tid) {
    const char* gh = (const char*)hi + (size_t)kc * 128;  // 64 bf16 = 128B
    const char* gl = (const char*)lo + (size_t)kc * 128;
#pragma unroll
    for (int q = 0; q < 2; ++q) {
        int idx = tid + 512 * q;
        int row = idx >> 3, seg = idx & 7;
        uint32_t so = SWZ((uint32_t)(row * 128 + seg * 16));
        size_t go = (size_t)row * 8192 + seg * 16;
        asm volatile("cp.async.cg.shared.global [%0], [%1], 16;"
                     :: "r"(dsth + so), "l"(gh + go) : "memory");
        asm volatile("cp.async.cg.shared.global [%0], [%1], 16;"
                     :: "r"(dstl + so), "l"(gl + go) : "memory");
    }
    asm volatile("cp.async.commit_group;" ::: "memory");
}

// Build BOTH A_hi and A_lo tiles for one K-chunk from one S read each.
// Exploits the 2-nonzero hat structure: row has (1-t) at col k, t at col k+1.
__device__ __forceinline__ void build_A2(const float* __restrict__ S, int bm,
                                         int kc, uint32_t ahi, uint32_t alo,
                                         int tid) {
#pragma unroll
    for (int q = 0; q < 2; ++q) {
        int idx = tid + 512 * q;
        int n = idx & 127;
        int il = idx >> 7;
        float sv = __ldg(&S[(size_t)(kc * 8 + il) * NTOT + bm + n]);
        int k = min((int)sv, 6);
        float t = sv - (float)k;
        float cl = 1.0f - t;
        __nv_bfloat162 h2 = __floats2bfloat162_rn(cl, t);  // .x=cl(lo16), .y=t(hi16)
        uint32_t Phi = *(uint32_t*)&h2;
        float rl = cl - __low2float(h2);
        float rt = t - __high2float(h2);
        __nv_bfloat162 l2 = __floats2bfloat162_rn(rl, rt);
        uint32_t Plo = *(uint32_t*)&l2;
        int j = k >> 1;
        int odd = k & 1;
        uint32_t eh = odd ? (Phi << 16) : Phi;   // word j content
        uint32_t el = odd ? (Plo << 16) : Plo;
        uint32_t sh = odd ? (Phi >> 16) : 0u;    // word j+1 content (odd only)
        uint32_t sl = odd ? (Plo >> 16) : 0u;
        uint32_t wh[4], wl[4];
#pragma unroll
        for (int m = 0; m < 4; ++m) {
            wh[m] = (m == j) ? eh : ((m == j + 1) ? sh : 0u);
            wl[m] = (m == j) ? el : ((m == j + 1) ? sl : 0u);
        }
        uint32_t off = SWZ((uint32_t)(n * 128 + il * 16));
        asm volatile("st.shared.v4.b32 [%0], {%1,%2,%3,%4};"
                     :: "r"(ahi + off), "r"(wh[0]), "r"(wh[1]), "r"(wh[2]), "r"(wh[3])
                     : "memory");
        asm volatile("st.shared.v4.b32 [%0], {%1,%2,%3,%4};"
                     :: "r"(alo + off), "r"(wl[0]), "r"(wl[1]), "r"(wl[2]), "r"(wl[3])
                     : "memory");
    }
}

__device__ __forceinline__ void ldsm4(uint32_t a, uint32_t& r0, uint32_t& r1,
                                      uint32_t& r2, uint32_t& r3) {
    asm volatile("ldmatrix.sync.aligned.m8n8.x4.shared.b16 {%0,%1,%2,%3}, [%4];"
                 : "=r"(r0), "=r"(r1), "=r"(r2), "=r"(r3) : "r"(a));
}

__device__ __forceinline__ void mma16816(float* d, const uint32_t* a,
                                         const uint32_t* b) {
    asm volatile(
        "mma.sync.aligned.m16n8k16.row.col.f32.bf16.bf16.f32 "
        "{%0,%1,%2,%3}, {%4,%5,%6,%7}, {%8,%9}, {%0,%1,%2,%3};"
        : "+f"(d[0]), "+f"(d[1]), "+f"(d[2]), "+f"(d[3])
        : "r"(a[0]), "r"(a[1]), "r"(a[2]), "r"(a[3]), "r"(b[0]), "r"(b[1]));
}

__global__ void __launch_bounds__(512, 1) apl_hmma_kernel(
    const float* __restrict__ S, const __nv_bfloat16* __restrict__ Vhi,
    const __nv_bfloat16* __restrict__ Vlo, float* __restrict__ out) {
    extern __shared__ char smem[];
    uint32_t sb = (smem_u32(smem) + 1023u) & ~1023u;
    const uint32_t AH = sb;                      // 2 x 16KB
    const uint32_t AL = sb + 2 * TILE16K;        // 2 x 16KB
    const uint32_t BH = sb + 4 * TILE16K;        // 3 x 16KB
    const uint32_t BL = sb + 7 * TILE16K;        // 3 x 16KB
    const int tid = threadIdx.x;
    const int lane = tid & 31;
    const int wid = tid >> 5;
    const int wm = wid & 3;             // 4 warp rows (32 each)
    const int wn = wid >> 2;            // 4 warp cols (32 each)
    const int bm = blockIdx.x * 128;
    const int bn = blockIdx.y * 128;

    const __nv_bfloat16* VhiB = Vhi + (size_t)bn * KTOT;
    const __nv_bfloat16* VloB = Vlo + (size_t)bn * KTOT;

    float acc[2][4][4];
#pragma unroll
    for (int mi = 0; mi < 2; ++mi)
#pragma unroll
        for (int nj = 0; nj < 4; ++nj)
#pragma unroll
            for (int u = 0; u < 4; ++u) acc[mi][nj][u] = 0.0f;

    // ldmatrix per-thread base offsets (pre-swizzle)
    uint32_t a_off[2], b_off[2];
#pragma unroll
    for (int mi = 0; mi < 2; ++mi) {
        int row = wm * 32 + mi * 16 + (lane & 15);
        a_off[mi] = (uint32_t)(row * 128 + (lane >> 4) * 16);
    }
#pragma unroll
    for (int ni = 0; ni < 2; ++ni) {
        int row = wn * 32 + ni * 16 + (lane & 7) + ((lane & 16) >> 1);
        b_off[ni] = (uint32_t)(row * 128 + ((lane >> 3) & 1) * 16);
    }

    // prologue
    load_B_pair(VhiB, VloB, 0, BH, BL, tid);
    load_B_pair(VhiB, VloB, 1, BH + TILE16K, BL + TILE16K, tid);
    build_A2(S, bm, 0, AH, AL, tid);

    for (int kc = 0; kc < NKC; ++kc) {
        if (kc < NKC - 2)
            asm volatile("cp.async.wait_group 1;" ::: "memory");
        else
            asm volatile("cp.async.wait_group 0;" ::: "memory");
        __syncthreads();   // B(kc) arrived; A(kc) built by all warps

        if (kc + 2 < NKC) {
            int s2 = (kc + 2) % 3;
            load_B_pair(VhiB, VloB, kc + 2, BH + s2 * TILE16K, BL + s2 * TILE16K, tid);
        }

        const uint32_t AHc = AH + (kc & 1) * TILE16K;
        const uint32_t ALc = AL + (kc & 1) * TILE16K;
        const uint32_t BHc = BH + (kc % 3) * TILE16K;
        const uint32_t BLc = BL + (kc % 3) * TILE16K;

#pragma unroll
        for (int kk = 0; kk < 4; ++kk) {
            uint32_t ah[2][4], al_[2][4], bh[4][2], bl_[4][2];
#pragma unroll
            for (int mi = 0; mi < 2; ++mi)
                ldsm4(AHc + SWZ(a_off[mi] + kk * 32),
                      ah[mi][0], ah[mi][1], ah[mi][2], ah[mi][3]);
#pragma unroll
            for (int ni = 0; ni < 2; ++ni) {
                uint32_t r0, r1, r2, r3;
                ldsm4(BHc + SWZ(b_off[ni] + kk * 32), r0, r1, r2, r3);
                bh[2 * ni][0] = r0; bh[2 * ni][1] = r1;
                bh[2 * ni + 1][0] = r2; bh[2 * ni + 1][1] = r3;
            }
#pragma unroll
            for (int mi = 0; mi < 2; ++mi)
#pragma unroll
                for (int nj = 0; nj < 4; ++nj)
                    mma16816(acc[mi][nj], ah[mi], bh[nj]);   // A_hi x B_hi

#pragma unroll
            for (int ni = 0; ni < 2; ++ni) {
                uint32_t r0, r1, r2, r3;
                ldsm4(BLc + SWZ(b_off[ni] + kk * 32), r0, r1, r2, r3);
                bl_[2 * ni][0] = r0; bl_[2 * ni][1] = r1;
                bl_[2 * ni + 1][0] = r2; bl_[2 * ni + 1][1] = r3;
            }
#pragma unroll
            for (int mi = 0; mi < 2; ++mi)
#pragma unroll
                for (int nj = 0; nj < 4; ++nj)
                    mma16816(acc[mi][nj], ah[mi], bl_[nj]);  // A_hi x B_lo

#pragma unroll
            for (int mi = 0; mi < 2; ++mi)
                ldsm4(ALc + SWZ(a_off[mi] + kk * 32),
                      al_[mi][0], al_[mi][1], al_[mi][2], al_[mi][3]);
#pragma unroll
            for (int mi = 0; mi < 2; ++mi)
#pragma unroll
                for (int nj = 0; nj < 4; ++nj)
                    mma16816(acc[mi][nj], al_[mi], bh[nj]);  // A_lo x B_hi
        }

        // build A(kc+1) into the other buffers (overlaps with MMA drain)
        if (kc + 1 < NKC)
            build_A2(S, bm, kc + 1, AH + ((kc + 1) & 1) * TILE16K,
                     AL + ((kc + 1) & 1) * TILE16K, tid);
    }

    // epilogue
#pragma unroll
    for (int mi = 0; mi < 2; ++mi) {
#pragma unroll
        for (int nj = 0; nj < 4; ++nj) {
            int row = bm + wm * 32 + mi * 16 + (lane >> 2);
            int col = bn + wn * 32 + nj * 8 + 2 * (lane & 3);
            float2* p0 = (float2*)&out[(size_t)row * DD + col];
            float2* p1 = (float2*)&out[(size_t)(row + 8) * DD + col];
            *p0 = make_float2(acc[mi][nj][0], acc[mi][nj][1]);
            *p1 = make_float2(acc[mi][nj][2], acc[mi][nj][3]);
        }
    }
}

// ---------------------------------------------------------------------------
// Scan: h[t] = (1-z) h[t-1] + z h_bar, z = sigmoid(zl)
// ---------------------------------------------------------------------------
__global__ __launch_bounds__(256) void scan_kernel(
    const float* __restrict__ zl, const float* __restrict__ hb,
    float* __restrict__ h) {
    int c = blockIdx.x * blockDim.x + threadIdx.x;
    if (c >= BD * DD) return;
    int b = c >> 9;
    int d = c & 511;
    size_t base = (size_t)b * TD * DD + d;
    float hc = 0.0f;
#pragma unroll 8
    for (int t = 0; t < TD; ++t) {
        size_t idx = base + (size_t)t * DD;
        float zv = 1.0f / (1.0f + expf(-zl[idx]));
        float hbv = hb[idx];
        hc = fmaf(zv, hbv - hc, hc);
        h[idx] = hc;
    }
}

// ---------------------------------------------------------------------------
// Max-abs norm, in place
// ---------------------------------------------------------------------------
__global__ __launch_bounds__(256) void norm_kernel(float* __restrict__ h, int rows) {
    int warp = (blockIdx.x * blockDim.x + threadIdx.x) >> 5;
    int lane = threadIdx.x & 31;
    if (warp >= rows) return;
    float4* row = (float4*)(h + (size_t)warp * DD);
    float4 vals[4];
    float m = 0.0f;
#pragma unroll
    for (int j = 0; j < 4; ++j) {
        vals[j] = row[lane + 32 * j];
        m = fmaxf(m, fmaxf(fmaxf(fabsf(vals[j].x), fabsf(vals[j].y)),
                           fmaxf(fabsf(vals[j].z), fabsf(vals[j].w))));
    }
#pragma unroll
    for (int off = 16; off; off >>= 1)
        m = fmaxf(m, __shfl_xor_sync(0xffffffffu, m, off));
    float inv = 1.0f / (m + 1e-6f);
#pragma unroll
    for (int j = 0; j < 4; ++j) {
        vals[j].x *= inv; vals[j].y *= inv; vals[j].z *= inv; vals[j].w *= inv;
        row[lane + 32 * j] = vals[j];
    }
}

// ---------------------------------------------------------------------------
// kernel_launch
// ---------------------------------------------------------------------------
extern "C" void kernel_launch(void* const* d_in, const int* in_sizes, int n_in,
                              void* d_out, int out_size) {
    const float* x   = (const float*)d_in[0];
    const float* pz0 = (const float*)d_in[1];
    const float* vz0 = (const float*)d_in[2];
    const float* ph0 = (const float*)d_in[3];
    const float* vh0 = (const float*)d_in[4];
    const float* pz1 = (const float*)d_in[5];
    const float* vz1 = (const float*)d_in[6];
    const float* ph1 = (const float*)d_in[7];
    const float* vh1 = (const float*)d_in[8];
    const float* po  = (const float*)d_in[9];
    const float* vo  = (const float*)d_in[10];

    const int N = in_sizes[0] / DD;  // 16384

    float *s, *zl, *hb;
    __nv_bfloat16 *vthi, *vtlo;
    cudaGetSymbolAddress((void**)&s,  g_s);
    cudaGetSymbolAddress((void**)&zl, g_zl);
    cudaGetSymbolAddress((void**)&hb, g_hbar);
    cudaGetSymbolAddress((void**)&vthi, g_vthi);
    cudaGetSymbolAddress((void**)&vtlo, g_vtlo);

    static int smem_set = 0;
    if (!smem_set) {
        cudaFuncSetAttribute(apl_hmma_kernel,
                             cudaFuncAttributeMaxDynamicSharedMemorySize, SMEM_REQ);
        smem_set = 1;
    }

    float* out = (float*)d_out;
    float* h1  = out + (size_t)N * DD;
    float* h2  = h1 + (size_t)N * DD;

    dim3 tgrid(DD / 32, N / 32);
    dim3 tblk(32, 8);
    dim3 spgrid(KTOT / 32, DD / 32);
    dim3 ggrid(N / 128, DD / 128);
    const int scan_blocks = (BD * DD + 255) / 256;
    const int norm_blocks = (N * 32 + 255) / 256;
    const size_t VSZ = (size_t)DD * KTOT;

    // precompute V^T hi/lo splits
    const float* vs[5] = {vz0, vh0, vz1, vh1, vo};
    for (int i = 0; i < 5; ++i)
        split_transpose_kernel<<<spgrid, tblk>>>(vs[i], vthi + i * VSZ, vtlo + i * VSZ);

    // ---- layer 0 ----
    build_s_kernel<<<tgrid, tblk>>>(x, pz0, s, N);
    apl_hmma_kernel<<<ggrid, 512, SMEM_REQ>>>(s, vthi + 0 * VSZ, vtlo + 0 * VSZ, zl);
    build_s_kernel<<<tgrid, tblk>>>(x, ph0, s, N);
    apl_hmma_kernel<<<ggrid, 512, SMEM_REQ>>>(s, vthi + 1 * VSZ, vtlo + 1 * VSZ, hb);
    scan_kernel<<<scan_blocks, 256>>>(zl, hb, h1);
    norm_kernel<<<norm_blocks, 256>>>(h1, N);

    // ---- layer 1 ----
    build_s_kernel<<<tgrid, tblk>>>(h1, pz1, s, N);
    apl_hmma_kernel<<<ggrid, 512, SMEM_REQ>>>(s, vthi + 2 * VSZ, vtlo + 2 * VSZ, zl);
    build_s_kernel<<<tgrid, tblk>>>(h1, ph1, s, N);
    apl_hmma_kernel<<<ggrid, 512, SMEM_REQ>>>(s, vthi + 3 * VSZ, vtlo + 3 * VSZ, hb);
    scan_kernel<<<scan_blocks, 256>>>(zl, hb, h2);
    norm_kernel<<<norm_blocks, 256>>>(h2, N);

    // ---- output APL ----
    build_s_kernel<<<tgrid, tblk>>>(h2, po, s, N);
    apl_hmma_kernel<<<ggrid, 512, SMEM_REQ>>>(s, vthi + 4 * VSZ, vtlo + 4 * VSZ, out);
}

// round 6
// speedup vs baseline: 2.2375x; 1.1926x over previous
#include <cuda_runtime.h>
#include <cuda_fp16.h>
#include <math.h>
#include <stdint.h>

// Problem constants
#define BD   8
#define TD   2048
#define DD   512
#define NTOT (BD * TD)     // 16384
#define KTOT 4096          // D * P
#define NKC  64            // K-chunks of 64 elements

// ---------------------------------------------------------------------------
// Scratch (device globals — no allocations allowed)
// ---------------------------------------------------------------------------
__device__ float g_s0[(size_t)DD * NTOT];       // s values, i-major (buffer 0)
__device__ float g_s1[(size_t)DD * NTOT];       // s values, i-major (buffer 1)
__device__ float g_zl[(size_t)NTOT * DD];       // z logits
__device__ float g_hbar[(size_t)NTOT * DD];     // h_bar
__device__ __half g_vthi[5][(size_t)DD * KTOT]; // V^T hi split (512 x 4096)
__device__ __half g_vtlo[5][(size_t)DD * KTOT]; // V^T lo split

// ---------------------------------------------------------------------------
// helpers
// ---------------------------------------------------------------------------
__device__ __forceinline__ uint32_t smem_u32(const void* p) {
    uint32_t a;
    asm("{ .reg .u64 t; cvta.to.shared.u64 t, %1; cvt.u32.u64 %0, t; }"
        : "=r"(a) : "l"(p));
    return a;
}

#define SWZ(x) ((x) ^ (((x) >> 3) & 0x70))

// ---------------------------------------------------------------------------
// build_s: s[i*N+n] = k + t  (searchsorted + clamped lerp parameter)
// ---------------------------------------------------------------------------
__global__ __launch_bounds__(256) void build_s_kernel(
    const float* __restrict__ X, const float* __restrict__ Pp,
    float* __restrict__ S, int N) {
    __shared__ float tile[32][33];
    int i0 = blockIdx.x * 32;
    int n0 = blockIdx.y * 32;
    int tx = threadIdx.x;
    int ty = threadIdx.y;
    int i = i0 + tx;

    float p[8];
#pragma unroll
    for (int j = 0; j < 8; ++j) p[j] = Pp[i * 8 + j];

#pragma unroll
    for (int r = 0; r < 4; ++r) {
        int nl = ty + 8 * r;
        int n = n0 + nl;
        float x = X[(size_t)n * DD + i];
        int k = 0;
        float pl = p[0], pr = p[1];
#pragma unroll
        for (int j = 1; j <= 6; ++j) {
            if (p[j] < x) { k = j; pl = p[j]; pr = p[j + 1]; }
        }
        float t = (x - pl) / (pr - pl);
        t = fminf(fmaxf(t, 0.0f), 1.0f);
        tile[nl][tx] = (float)k + t;
    }
    __syncthreads();
#pragma unroll
    for (int r = 0; r < 4; ++r) {
        int il = ty + 8 * r;
        S[(size_t)(i0 + il) * N + n0 + tx] = tile[tx][il];
    }
}

// ---------------------------------------------------------------------------
// split_transpose (fused over up to 3 matrices via blockIdx.z):
// v (4096 x 512 f32) -> Vt_hi/Vt_lo (512 x 4096 fp16)
// ---------------------------------------------------------------------------
__global__ __launch_bounds__(256) void split_transpose_kernel(
    const float* __restrict__ va, const float* __restrict__ vb,
    const float* __restrict__ vc, __half* __restrict__ hi_base,
    __half* __restrict__ lo_base, int ibase) {
    const size_t VSZ = (size_t)DD * KTOT;
    int z = blockIdx.z;
    const float* v = (z == 0) ? va : (z == 1) ? vb : vc;
    __half* hi = hi_base + (size_t)(ibase + z) * VSZ;
    __half* lo = lo_base + (size_t)(ibase + z) * VSZ;

    __shared__ float t[32][33];
    int k0 = blockIdx.x * 32;
    int o0 = blockIdx.y * 32;
    int tx = threadIdx.x, ty = threadIdx.y;
#pragma unroll
    for (int r = 0; r < 4; ++r)
        t[ty + 8 * r][tx] = v[(size_t)(k0 + ty + 8 * r) * DD + o0 + tx];
    __syncthreads();
#pragma unroll
    for (int r = 0; r < 4; ++r) {
        float val = t[tx][ty + 8 * r];
        __half h = __float2half_rn(val);
        float res = val - __half2float(h);
        size_t idx = (size_t)(o0 + ty + 8 * r) * KTOT + k0 + tx;
        hi[idx] = h;
        lo[idx] = __float2half_rn(res);
    }
}

// ---------------------------------------------------------------------------
// APL HMMA GEMM, fp16 2-term split per K-chunk:
//   out += A_hi x B_hi + A_hi x B_lo
// 512 threads, 16 warps (4x4), warp tile 32x32, CTA tile 128(M)x128(N).
// SMEM: A_hi[2] (built on the fly), B_hi[3], B_lo[3] (cp.async rings).
// ---------------------------------------------------------------------------
#define TILE16K 16384
#define SMEM_REQ (1024 + 2 * TILE16K + 6 * TILE16K)

__device__ __forceinline__ void load_B_pair(const __half* hi, const __half* lo,
                                            int kc, uint32_t dsth, uint32_t dstl,
                                            int tid) {
    const char* gh = (const char*)hi + (size_t)kc * 128;  // 64 fp16 = 128B
    const char* gl = (const char*)lo + (size_t)kc * 128;
#pragma unroll
    for (int q = 0; q < 2; ++q) {
        int idx = tid + 512 * q;
        int row = idx >> 3, seg = idx & 7;
        uint32_t so = SWZ((uint32_t)(row * 128 + seg * 16));
        size_t go = (size_t)row * 8192 + seg * 16;
        asm volatile("cp.async.cg.shared.global [%0], [%1], 16;"
                     :: "r"(dsth + so), "l"(gh + go) : "memory");
        asm volatile("cp.async.cg.shared.global [%0], [%1], 16;"
                     :: "r"(dstl + so), "l"(gl + go) : "memory");
    }
    asm volatile("cp.async.commit_group;" ::: "memory");
}

// Build A_hi tile for one K-chunk: row has fp16(1-t) at col k, fp16(t) at k+1.
__device__ __forceinline__ void build_A(const float* __restrict__ S, int bm,
                                        int kc, uint32_t ahi, int tid) {
#pragma unroll
    for (int q = 0; q < 2; ++q) {
        int idx = tid + 512 * q;
        int n = idx & 127;
        int il = idx >> 7;
        float sv = __ldg(&S[(size_t)(kc * 8 + il) * NTOT + bm + n]);
        int k = min((int)sv, 6);
        float t = sv - (float)k;
        __half2 h2 = __floats2half2_rn(1.0f - t, t);  // .x=1-t(lo16), .y=t(hi16)
        uint32_t Phi = *(uint32_t*)&h2;
        int j = k >> 1;
        int odd = k & 1;
        uint32_t e = odd ? (Phi << 16) : Phi;   // word j content
        uint32_t sft = odd ? (Phi >> 16) : 0u;  // word j+1 content (odd only)
        uint32_t w[4];
#pragma unroll
        for (int m = 0; m < 4; ++m)
            w[m] = (m == j) ? e : ((m == j + 1) ? sft : 0u);
        uint32_t off = SWZ((uint32_t)(n * 128 + il * 16));
        asm volatile("st.shared.v4.b32 [%0], {%1,%2,%3,%4};"
                     :: "r"(ahi + off), "r"(w[0]), "r"(w[1]), "r"(w[2]), "r"(w[3])
                     : "memory");
    }
}

__device__ __forceinline__ void ldsm4(uint32_t a, uint32_t& r0, uint32_t& r1,
                                      uint32_t& r2, uint32_t& r3) {
    asm volatile("ldmatrix.sync.aligned.m8n8.x4.shared.b16 {%0,%1,%2,%3}, [%4];"
                 : "=r"(r0), "=r"(r1), "=r"(r2), "=r"(r3) : "r"(a));
}

__device__ __forceinline__ void mma16816(float* d, const uint32_t* a,
                                         const uint32_t* b) {
    asm volatile(
        "mma.sync.aligned.m16n8k16.row.col.f32.f16.f16.f32 "
        "{%0,%1,%2,%3}, {%4,%5,%6,%7}, {%8,%9}, {%0,%1,%2,%3};"
        : "+f"(d[0]), "+f"(d[1]), "+f"(d[2]), "+f"(d[3])
        : "r"(a[0]), "r"(a[1]), "r"(a[2]), "r"(a[3]), "r"(b[0]), "r"(b[1]));
}

__global__ void __launch_bounds__(512, 1) apl_hmma_kernel(
    const float* __restrict__ S, const __half* __restrict__ Vhi,
    const __half* __restrict__ Vlo, float* __restrict__ out) {
    extern __shared__ char smem[];
    uint32_t sb = (smem_u32(smem) + 1023u) & ~1023u;
    const uint32_t AH = sb;                      // 2 x 16KB
    const uint32_t BH = sb + 2 * TILE16K;        // 3 x 16KB
    const uint32_t BL = sb + 5 * TILE16K;        // 3 x 16KB
    const int tid = threadIdx.x;
    const int lane = tid & 31;
    const int wid = tid >> 5;
    const int wm = wid & 3;             // 4 warp rows (32 each)
    const int wn = wid >> 2;            // 4 warp cols (32 each)
    const int bm = blockIdx.x * 128;
    const int bn = blockIdx.y * 128;

    const __half* VhiB = Vhi + (size_t)bn * KTOT;
    const __half* VloB = Vlo + (size_t)bn * KTOT;

    float acc[2][4][4];
#pragma unroll
    for (int mi = 0; mi < 2; ++mi)
#pragma unroll
        for (int nj = 0; nj < 4; ++nj)
#pragma unroll
            for (int u = 0; u < 4; ++u) acc[mi][nj][u] = 0.0f;

    // ldmatrix per-thread base offsets (pre-swizzle)
    uint32_t a_off[2], b_off[2];
#pragma unroll
    for (int mi = 0; mi < 2; ++mi) {
        int row = wm * 32 + mi * 16 + (lane & 15);
        a_off[mi] = (uint32_t)(row * 128 + (lane >> 4) * 16);
    }
#pragma unroll
    for (int ni = 0; ni < 2; ++ni) {
        int row = wn * 32 + ni * 16 + (lane & 7) + ((lane & 16) >> 1);
        b_off[ni] = (uint32_t)(row * 128 + ((lane >> 3) & 1) * 16);
    }

    // prologue
    load_B_pair(VhiB, VloB, 0, BH, BL, tid);
    load_B_pair(VhiB, VloB, 1, BH + TILE16K, BL + TILE16K, tid);
    build_A(S, bm, 0, AH, tid);

    for (int kc = 0; kc < NKC; ++kc) {
        if (kc < NKC - 2)
            asm volatile("cp.async.wait_group 1;" ::: "memory");
        else
            asm volatile("cp.async.wait_group 0;" ::: "memory");
        __syncthreads();   // B(kc) arrived; A(kc) built by all warps

        if (kc + 2 < NKC) {
            int s2 = (kc + 2) % 3;
            load_B_pair(VhiB, VloB, kc + 2, BH + s2 * TILE16K, BL + s2 * TILE16K, tid);
        }

        const uint32_t AHc = AH + (kc & 1) * TILE16K;
        const uint32_t BHc = BH + (kc % 3) * TILE16K;
        const uint32_t BLc = BL + (kc % 3) * TILE16K;

#pragma unroll
        for (int kk = 0; kk < 4; ++kk) {
            uint32_t ah[2][4], bh[4][2], bl_[4][2];
#pragma unroll
            for (int mi = 0; mi < 2; ++mi)
                ldsm4(AHc + SWZ(a_off[mi] + kk * 32),
                      ah[mi][0], ah[mi][1], ah[mi][2], ah[mi][3]);
#pragma unroll
            for (int ni = 0; ni < 2; ++ni) {
                uint32_t r0, r1, r2, r3;
                ldsm4(BHc + SWZ(b_off[ni] + kk * 32), r0, r1, r2, r3);
                bh[2 * ni][0] = r0; bh[2 * ni][1] = r1;
                bh[2 * ni + 1][0] = r2; bh[2 * ni + 1][1] = r3;
            }
#pragma unroll
            for (int mi = 0; mi < 2; ++mi)
#pragma unroll
                for (int nj = 0; nj < 4; ++nj)
                    mma16816(acc[mi][nj], ah[mi], bh[nj]);   // A_hi x B_hi

#pragma unroll
            for (int ni = 0; ni < 2; ++ni) {
                uint32_t r0, r1, r2, r3;
                ldsm4(BLc + SWZ(b_off[ni] + kk * 32), r0, r1, r2, r3);
                bl_[2 * ni][0] = r0; bl_[2 * ni][1] = r1;
                bl_[2 * ni + 1][0] = r2; bl_[2 * ni + 1][1] = r3;
            }
#pragma unroll
            for (int mi = 0; mi < 2; ++mi)
#pragma unroll
                for (int nj = 0; nj < 4; ++nj)
                    mma16816(acc[mi][nj], ah[mi], bl_[nj]);  // A_hi x B_lo
        }

        // build A(kc+1) into the other buffer (overlaps with MMA drain)
        if (kc + 1 < NKC)
            build_A(S, bm, kc + 1, AH + ((kc + 1) & 1) * TILE16K, tid);
    }

    // epilogue
#pragma unroll
    for (int mi = 0; mi < 2; ++mi) {
#pragma unroll
        for (int nj = 0; nj < 4; ++nj) {
            int row = bm + wm * 32 + mi * 16 + (lane >> 2);
            int col = bn + wn * 32 + nj * 8 + 2 * (lane & 3);
            float2* p0 = (float2*)&out[(size_t)row * DD + col];
            float2* p1 = (float2*)&out[(size_t)(row + 8) * DD + col];
            *p0 = make_float2(acc[mi][nj][0], acc[mi][nj][1]);
            *p1 = make_float2(acc[mi][nj][2], acc[mi][nj][3]);
        }
    }
}

// ---------------------------------------------------------------------------
// Scan: h[t] = (1-z) h[t-1] + z h_bar, z = sigmoid(zl)
// ---------------------------------------------------------------------------
__global__ __launch_bounds__(256) void scan_kernel(
    const float* __restrict__ zl, const float* __restrict__ hb,
    float* __restrict__ h) {
    int c = blockIdx.x * blockDim.x + threadIdx.x;
    if (c >= BD * DD) return;
    int b = c >> 9;
    int d = c & 511;
    size_t base = (size_t)b * TD * DD + d;
    float hc = 0.0f;
#pragma unroll 8
    for (int t = 0; t < TD; ++t) {
        size_t idx = base + (size_t)t * DD;
        float zv = 1.0f / (1.0f + expf(-zl[idx]));
        float hbv = hb[idx];
        hc = fmaf(zv, hbv - hc, hc);
        h[idx] = hc;
    }
}

// ---------------------------------------------------------------------------
// Max-abs norm, in place
// ---------------------------------------------------------------------------
__global__ __launch_bounds__(256) void norm_kernel(float* __restrict__ h, int rows) {
    int warp = (blockIdx.x * blockDim.x + threadIdx.x) >> 5;
    int lane = threadIdx.x & 31;
    if (warp >= rows) return;
    float4* row = (float4*)(h + (size_t)warp * DD);
    float4 vals[4];
    float m = 0.0f;
#pragma unroll
    for (int j = 0; j < 4; ++j) {
        vals[j] = row[lane + 32 * j];
        m = fmaxf(m, fmaxf(fmaxf(fabsf(vals[j].x), fabsf(vals[j].y)),
                           fmaxf(fabsf(vals[j].z), fabsf(vals[j].w))));
    }
#pragma unroll
    for (int off = 16; off; off >>= 1)
        m = fmaxf(m, __shfl_xor_sync(0xffffffffu, m, off));
    float inv = 1.0f / (m + 1e-6f);
#pragma unroll
    for (int j = 0; j < 4; ++j) {
        vals[j].x *= inv; vals[j].y *= inv; vals[j].z *= inv; vals[j].w *= inv;
        row[lane + 32 * j] = vals[j];
    }
}

// ---------------------------------------------------------------------------
// kernel_launch
// Launch order is arranged so launch #6 is an apl_hmma_kernel (ncu -s 5 -c 1).
// ---------------------------------------------------------------------------
extern "C" void kernel_launch(void* const* d_in, const int* in_sizes, int n_in,
                              void* d_out, int out_size) {
    const float* x   = (const float*)d_in[0];
    const float* pz0 = (const float*)d_in[1];
    const float* vz0 = (const float*)d_in[2];
    const float* ph0 = (const float*)d_in[3];
    const float* vh0 = (const float*)d_in[4];
    const float* pz1 = (const float*)d_in[5];
    const float* vz1 = (const float*)d_in[6];
    const float* ph1 = (const float*)d_in[7];
    const float* vh1 = (const float*)d_in[8];
    const float* po  = (const float*)d_in[9];
    const float* vo  = (const float*)d_in[10];

    const int N = in_sizes[0] / DD;  // 16384

    float *s0, *s1, *zl, *hb;
    __half *vthi, *vtlo;
    cudaGetSymbolAddress((void**)&s0, g_s0);
    cudaGetSymbolAddress((void**)&s1, g_s1);
    cudaGetSymbolAddress((void**)&zl, g_zl);
    cudaGetSymbolAddress((void**)&hb, g_hbar);
    cudaGetSymbolAddress((void**)&vthi, g_vthi);
    cudaGetSymbolAddress((void**)&vtlo, g_vtlo);

    static int smem_set = 0;
    if (!smem_set) {
        cudaFuncSetAttribute(apl_hmma_kernel,
                             cudaFuncAttributeMaxDynamicSharedMemorySize, SMEM_REQ);
        smem_set = 1;
    }

    float* out = (float*)d_out;
    float* h1  = out + (size_t)N * DD;
    float* h2  = h1 + (size_t)N * DD;

    dim3 tgrid(DD / 32, N / 32);
    dim3 tblk(32, 8);
    dim3 sp3(KTOT / 32, DD / 32, 3);
    dim3 sp2(KTOT / 32, DD / 32, 2);
    dim3 ggrid(N / 128, DD / 128);
    const int scan_blocks = (BD * DD + 255) / 256;
    const int norm_blocks = (N * 32 + 255) / 256;
    const size_t VSZ = (size_t)DD * KTOT;

    // [1][2] precompute V^T hi/lo splits (order: vz0, vh0, vz1 | vh1, vo)
    split_transpose_kernel<<<sp3, tblk>>>(vz0, vh0, vz1, vthi, vtlo, 0);
    split_transpose_kernel<<<sp2, tblk>>>(vh1, vo, vo, vthi, vtlo, 3);

    // ---- layer 0 ----
    build_s_kernel<<<tgrid, tblk>>>(x, pz0, s0, N);                     // [3]
    build_s_kernel<<<tgrid, tblk>>>(x, ph0, s1, N);                     // [4]
    apl_hmma_kernel<<<ggrid, 512, SMEM_REQ>>>(s0, vthi + 0 * VSZ, vtlo + 0 * VSZ, zl);  // [5]
    apl_hmma_kernel<<<ggrid, 512, SMEM_REQ>>>(s1, vthi + 1 * VSZ, vtlo + 1 * VSZ, hb);  // [6] <- profiled
    scan_kernel<<<scan_blocks, 256>>>(zl, hb, h1);
    norm_kernel<<<norm_blocks, 256>>>(h1, N);

    // ---- layer 1 ----
    build_s_kernel<<<tgrid, tblk>>>(h1, pz1, s0, N);
    build_s_kernel<<<tgrid, tblk>>>(h1, ph1, s1, N);
    apl_hmma_kernel<<<ggrid, 512, SMEM_REQ>>>(s0, vthi + 2 * VSZ, vtlo + 2 * VSZ, zl);
    apl_hmma_kernel<<<ggrid, 512, SMEM_REQ>>>(s1, vthi + 3 * VSZ, vtlo + 3 * VSZ, hb);
    scan_kernel<<<scan_blocks, 256>>>(zl, hb, h2);
    norm_kernel<<<norm_blocks, 256>>>(h2, N);

    // ---- output APL ----
    build_s_kernel<<<tgrid, tblk>>>(h2, po, s0, N);
    apl_hmma_kernel<<<ggrid, 512, SMEM_REQ>>>(s0, vthi + 4 * VSZ, vtlo + 4 * VSZ, out);
}

// round 7
// speedup vs baseline: 3.7800x; 1.6894x over previous
#include <cuda_runtime.h>
#include <cuda_fp16.h>
#include <math.h>
#include <stdint.h>

// Problem constants
#define BD   8
#define TD   2048
#define DD   512
#define NTOT (BD * TD)     // 16384
#define KTOT 4096          // D * P
#define NKC  64            // K-chunks of 64 elements
#define SEG  16
#define SEGLEN (TD / SEG)  // 128

// ---------------------------------------------------------------------------
// Scratch (device globals — no allocations allowed)
// ---------------------------------------------------------------------------
__device__ float g_s0[(size_t)DD * NTOT];
__device__ float g_s1[(size_t)DD * NTOT];
__device__ float g_zl[(size_t)NTOT * DD];
__device__ float g_hbar[(size_t)NTOT * DD];
// Pre-swizzled chunk tiles: [layer][nb(4)][kc(64)] each 16KB (128 rows x 64 cols fp16)
__device__ __half g_bt_hi[5][(size_t)4 * 64 * 8192];
__device__ __half g_bt_lo[5][(size_t)4 * 64 * 8192];
// scan scratch
__device__ float g_scanA[BD * SEG * DD];
__device__ float g_scanB[BD * SEG * DD];
__device__ float g_scanH[BD * SEG * DD];

// ---------------------------------------------------------------------------
// helpers
// ---------------------------------------------------------------------------
__device__ __forceinline__ uint32_t smem_u32(const void* p) {
    uint32_t a;
    asm("{ .reg .u64 t; cvta.to.shared.u64 t, %1; cvt.u32.u64 %0, t; }"
        : "=r"(a) : "l"(p));
    return a;
}

#define SWZ(x) ((x) ^ (((x) >> 3) & 0x70))

__device__ __forceinline__ void mbar_init(uint32_t a, uint32_t cnt) {
    asm volatile("mbarrier.init.shared.b64 [%0], %1;" :: "r"(a), "r"(cnt) : "memory");
}

__device__ __forceinline__ void mbar_wait(uint32_t a, uint32_t ph) {
    asm volatile(
        "{\n\t.reg .pred P;\n\t"
        "W%=:\n\t"
        "mbarrier.try_wait.parity.acquire.cta.shared::cta.b64 P, [%0], %1, 0x989680;\n\t"
        "@P bra.uni D%=;\n\t"
        "bra.uni W%=;\n\t"
        "D%=:\n\t}"
        :: "r"(a), "r"(ph) : "memory");
}

__device__ __forceinline__ void mbar_expect_tx(uint32_t a, uint32_t bytes) {
    asm volatile("mbarrier.arrive.expect_tx.shared.b64 _, [%0], %1;"
                 :: "r"(a), "r"(bytes) : "memory");
}

__device__ __forceinline__ void bulk_ld(uint32_t dst, const void* src,
                                        uint32_t bytes, uint32_t mbar) {
    asm volatile(
        "cp.async.bulk.shared::cluster.global.mbarrier::complete_tx::bytes "
        "[%0], [%1], %2, [%3];"
        :: "r"(dst), "l"(src), "r"(bytes), "r"(mbar) : "memory");
}

// ---------------------------------------------------------------------------
// build_s: s[i*N+n] = k + t  (searchsorted + clamped lerp parameter)
// ---------------------------------------------------------------------------
__global__ __launch_bounds__(256) void build_s_kernel(
    const float* __restrict__ X, const float* __restrict__ Pp,
    float* __restrict__ S, int N) {
    __shared__ float tile[32][33];
    int i0 = blockIdx.x * 32;
    int n0 = blockIdx.y * 32;
    int tx = threadIdx.x;
    int ty = threadIdx.y;
    int i = i0 + tx;

    float p[8];
#pragma unroll
    for (int j = 0; j < 8; ++j) p[j] = Pp[i * 8 + j];

#pragma unroll
    for (int r = 0; r < 4; ++r) {
        int nl = ty + 8 * r;
        int n = n0 + nl;
        float x = X[(size_t)n * DD + i];
        int k = 0;
        float pl = p[0], pr = p[1];
#pragma unroll
        for (int j = 1; j <= 6; ++j) {
            if (p[j] < x) { k = j; pl = p[j]; pr = p[j + 1]; }
        }
        float t = (x - pl) / (pr - pl);
        t = fminf(fmaxf(t, 0.0f), 1.0f);
        tile[nl][tx] = (float)k + t;
    }
    __syncthreads();
#pragma unroll
    for (int r = 0; r < 4; ++r) {
        int il = ty + 8 * r;
        S[(size_t)(i0 + il) * N + n0 + tx] = tile[tx][il];
    }
}

// ---------------------------------------------------------------------------
// split_chunk: v (4096 x 512 f32) -> pre-swizzled 16KB chunk tiles, fp16 hi/lo.
// grid (64 kc, 4 nb, 5 layer), block 256.
// tile[r (=out col o), c (=k within chunk)] = v[kc*64+c][nb*128+r]
// ---------------------------------------------------------------------------
__global__ __launch_bounds__(256) void split_chunk_kernel(
    const float* __restrict__ v0, const float* __restrict__ v1,
    const float* __restrict__ v2, const float* __restrict__ v3,
    const float* __restrict__ v4) {
    int kc = blockIdx.x, nb = blockIdx.y, layer = blockIdx.z;
    const float* v = (layer == 0) ? v0 : (layer == 1) ? v1 :
                     (layer == 2) ? v2 : (layer == 3) ? v3 : v4;
    size_t tile_off = ((size_t)layer * 256 + nb * 64 + kc) << 14;  // bytes
    char* hib = (char*)g_bt_hi + tile_off;
    char* lob = (char*)g_bt_lo + tile_off;

    int r = threadIdx.x & 127;
    int chalf = threadIdx.x >> 7;  // 0..1
#pragma unroll
    for (int j = 0; j < 32; ++j) {
        int c = chalf * 32 + j;
        float val = v[(size_t)(kc * 64 + c) * DD + nb * 128 + r];
        __half h = __float2half_rn(val);
        float res = val - __half2float(h);
        uint32_t off = SWZ((uint32_t)(r * 128 + c * 2));
        *(__half*)(hib + off) = h;
        *(__half*)(lob + off) = __float2half_rn(res);
    }
}

// ---------------------------------------------------------------------------
// APL HMMA GEMM, fp16 2-term split, B loaded via cp.async.bulk (16KB tiles).
// 512 threads, 16 warps (4x4), warp tile 32x32, CTA tile 128(M)x128(N).
// ---------------------------------------------------------------------------
#define TILE16K 16384
#define SMEM_REQ (1024 + 2 * TILE16K + 6 * TILE16K)

// Build A_hi tile for one K-chunk: row has fp16(1-t) at col k, fp16(t) at k+1.
__device__ __forceinline__ void build_A(const float* __restrict__ S, int bm,
                                        int kc, uint32_t ahi, int tid) {
#pragma unroll
    for (int q = 0; q < 2; ++q) {
        int idx = tid + 512 * q;
        int n = idx & 127;
        int il = idx >> 7;
        float sv = __ldg(&S[(size_t)(kc * 8 + il) * NTOT + bm + n]);
        int k = min((int)sv, 6);
        float t = sv - (float)k;
        __half2 h2 = __floats2half2_rn(1.0f - t, t);
        uint32_t Phi = *(uint32_t*)&h2;
        int j = k >> 1;
        int odd = k & 1;
        uint32_t e = odd ? (Phi << 16) : Phi;
        uint32_t sft = odd ? (Phi >> 16) : 0u;
        uint32_t w[4];
#pragma unroll
        for (int m = 0; m < 4; ++m)
            w[m] = (m == j) ? e : ((m == j + 1) ? sft : 0u);
        uint32_t off = SWZ((uint32_t)(n * 128 + il * 16));
        asm volatile("st.shared.v4.b32 [%0], {%1,%2,%3,%4};"
                     :: "r"(ahi + off), "r"(w[0]), "r"(w[1]), "r"(w[2]), "r"(w[3])
                     : "memory");
    }
}

__device__ __forceinline__ void ldsm4(uint32_t a, uint32_t& r0, uint32_t& r1,
                                      uint32_t& r2, uint32_t& r3) {
    asm volatile("ldmatrix.sync.aligned.m8n8.x4.shared.b16 {%0,%1,%2,%3}, [%4];"
                 : "=r"(r0), "=r"(r1), "=r"(r2), "=r"(r3) : "r"(a));
}

__device__ __forceinline__ void mma16816(float* d, const uint32_t* a,
                                         const uint32_t* b) {
    asm volatile(
        "mma.sync.aligned.m16n8k16.row.col.f32.f16.f16.f32 "
        "{%0,%1,%2,%3}, {%4,%5,%6,%7}, {%8,%9}, {%0,%1,%2,%3};"
        : "+f"(d[0]), "+f"(d[1]), "+f"(d[2]), "+f"(d[3])
        : "r"(a[0]), "r"(a[1]), "r"(a[2]), "r"(a[3]), "r"(b[0]), "r"(b[1]));
}

__global__ void __launch_bounds__(512, 1) apl_hmma_kernel(
    const float* __restrict__ S, const __half* __restrict__ Bhi,
    const __half* __restrict__ Blo, float* __restrict__ out) {
    extern __shared__ char smem[];
    uint32_t sb = (smem_u32(smem) + 1023u) & ~1023u;
    const uint32_t MB = sb;                      // 3 mbarriers @ +0,+8,+16
    const uint32_t AH = sb + 1024;               // 2 x 16KB
    const uint32_t BH = AH + 2 * TILE16K;        // 3 x 16KB
    const uint32_t BL = BH + 3 * TILE16K;        // 3 x 16KB
    const int tid = threadIdx.x;
    const int lane = tid & 31;
    const int wid = tid >> 5;
    const int wm = wid & 3;
    const int wn = wid >> 2;
    const int bm = blockIdx.x * 128;
    const int nb = blockIdx.y;

    // chunk-contiguous B source for this column block
    const char* hsrc = (const char*)Bhi + ((size_t)nb * 64 << 14);
    const char* lsrc = (const char*)Blo + ((size_t)nb * 64 << 14);

    if (tid == 0) {
        mbar_init(MB + 0, 1);
        mbar_init(MB + 8, 1);
        mbar_init(MB + 16, 1);
        asm volatile("fence.proxy.async.shared::cta;" ::: "memory");
    }
    __syncthreads();

    float acc[2][4][4];
#pragma unroll
    for (int mi = 0; mi < 2; ++mi)
#pragma unroll
        for (int nj = 0; nj < 4; ++nj)
#pragma unroll
            for (int u = 0; u < 4; ++u) acc[mi][nj][u] = 0.0f;

    uint32_t a_off[2], b_off[2];
#pragma unroll
    for (int mi = 0; mi < 2; ++mi) {
        int row = wm * 32 + mi * 16 + (lane & 15);
        a_off[mi] = (uint32_t)(row * 128 + (lane >> 4) * 16);
    }
#pragma unroll
    for (int ni = 0; ni < 2; ++ni) {
        int row = wn * 32 + ni * 16 + (lane & 7) + ((lane & 16) >> 1);
        b_off[ni] = (uint32_t)(row * 128 + ((lane >> 3) & 1) * 16);
    }

    // prologue: issue chunks 0,1 into stages 0,1; build A(0)
    if (tid == 0) {
#pragma unroll
        for (int c = 0; c < 2; ++c) {
            mbar_expect_tx(MB + c * 8, 2 * TILE16K);
            bulk_ld(BH + c * TILE16K, hsrc + ((size_t)c << 14), TILE16K, MB + c * 8);
            bulk_ld(BL + c * TILE16K, lsrc + ((size_t)c << 14), TILE16K, MB + c * 8);
        }
    }
    build_A(S, bm, 0, AH, tid);

    for (int kc = 0; kc < NKC; ++kc) {
        int st = kc % 3;
        uint32_t parity = (uint32_t)((kc / 3) & 1);
        mbar_wait(MB + st * 8, parity);
        __syncthreads();   // B(kc) ready; A(kc) built; all done with kc-1

        if (tid == 0 && kc + 2 < NKC) {
            int s2 = (kc + 2) % 3;
            mbar_expect_tx(MB + s2 * 8, 2 * TILE16K);
            bulk_ld(BH + s2 * TILE16K, hsrc + ((size_t)(kc + 2) << 14), TILE16K, MB + s2 * 8);
            bulk_ld(BL + s2 * TILE16K, lsrc + ((size_t)(kc + 2) << 14), TILE16K, MB + s2 * 8);
        }

        const uint32_t AHc = AH + (kc & 1) * TILE16K;
        const uint32_t BHc = BH + st * TILE16K;
        const uint32_t BLc = BL + st * TILE16K;

#pragma unroll
        for (int kk = 0; kk < 4; ++kk) {
            uint32_t ah[2][4], bh[4][2], bl_[4][2];
#pragma unroll
            for (int mi = 0; mi < 2; ++mi)
                ldsm4(AHc + SWZ(a_off[mi] + kk * 32),
                      ah[mi][0], ah[mi][1], ah[mi][2], ah[mi][3]);
#pragma unroll
            for (int ni = 0; ni < 2; ++ni) {
                uint32_t r0, r1, r2, r3;
                ldsm4(BHc + SWZ(b_off[ni] + kk * 32), r0, r1, r2, r3);
                bh[2 * ni][0] = r0; bh[2 * ni][1] = r1;
                bh[2 * ni + 1][0] = r2; bh[2 * ni + 1][1] = r3;
            }
#pragma unroll
            for (int mi = 0; mi < 2; ++mi)
#pragma unroll
                for (int nj = 0; nj < 4; ++nj)
                    mma16816(acc[mi][nj], ah[mi], bh[nj]);

#pragma unroll
            for (int ni = 0; ni < 2; ++ni) {
                uint32_t r0, r1, r2, r3;
                ldsm4(BLc + SWZ(b_off[ni] + kk * 32), r0, r1, r2, r3);
                bl_[2 * ni][0] = r0; bl_[2 * ni][1] = r1;
                bl_[2 * ni + 1][0] = r2; bl_[2 * ni + 1][1] = r3;
            }
#pragma unroll
            for (int mi = 0; mi < 2; ++mi)
#pragma unroll
                for (int nj = 0; nj < 4; ++nj)
                    mma16816(acc[mi][nj], ah[mi], bl_[nj]);
        }

        if (kc + 1 < NKC)
            build_A(S, bm, kc + 1, AH + ((kc + 1) & 1) * TILE16K, tid);
    }

    // epilogue
#pragma unroll
    for (int mi = 0; mi < 2; ++mi) {
#pragma unroll
        for (int nj = 0; nj < 4; ++nj) {
            int row = bm + wm * 32 + mi * 16 + (lane >> 2);
            int col = nb * 128 + wn * 32 + nj * 8 + 2 * (lane & 3);
            float2* p0 = (float2*)&out[(size_t)row * DD + col];
            float2* p1 = (float2*)&out[(size_t)(row + 8) * DD + col];
            *p0 = make_float2(acc[mi][nj][0], acc[mi][nj][1]);
            *p1 = make_float2(acc[mi][nj][2], acc[mi][nj][3]);
        }
    }
}

// ---------------------------------------------------------------------------
// Segmented scan (3 passes). h[t] = (1-z) h[t-1] + z h_bar, z = sigmoid(zl).
// ---------------------------------------------------------------------------
__global__ __launch_bounds__(256) void scan_p1(
    const float* __restrict__ zl, const float* __restrict__ hb) {
    int gid = blockIdx.x * blockDim.x + threadIdx.x;  // (b*SEG+seg)*DD + d
    if (gid >= BD * SEG * DD) return;
    int d = gid & 511;
    int bs = gid >> 9;
    int seg = bs & (SEG - 1);
    int b = bs / SEG;
    size_t base = (size_t)b * TD * DD + (size_t)seg * SEGLEN * DD + d;
    float A = 1.0f, Bv = 0.0f;
#pragma unroll 8
    for (int t = 0; t < SEGLEN; ++t) {
        size_t idx = base + (size_t)t * DD;
        float zv = 1.0f / (1.0f + expf(-zl[idx]));
        float a = 1.0f - zv;
        float bb = zv * hb[idx];
        A *= a;
        Bv = fmaf(a, Bv, bb);
    }
    g_scanA[gid] = A;
    g_scanB[gid] = Bv;
}

__global__ __launch_bounds__(256) void scan_p2() {
    int c = blockIdx.x * blockDim.x + threadIdx.x;  // b*DD + d
    if (c >= BD * DD) return;
    int d = c & 511;
    int b = c >> 9;
    float h = 0.0f;
#pragma unroll
    for (int seg = 0; seg < SEG; ++seg) {
        int gid = ((b * SEG + seg) << 9) + d;
        g_scanH[gid] = h;
        h = fmaf(g_scanA[gid], h, g_scanB[gid]);
    }
}

__global__ __launch_bounds__(256) void scan_p3(
    const float* __restrict__ zl, const float* __restrict__ hb,
    float* __restrict__ h) {
    int gid = blockIdx.x * blockDim.x + threadIdx.x;
    if (gid >= BD * SEG * DD) return;
    int d = gid & 511;
    int bs = gid >> 9;
    int seg = bs & (SEG - 1);
    int b = bs / SEG;
    size_t base = (size_t)b * TD * DD + (size_t)seg * SEGLEN * DD + d;
    float hc = g_scanH[gid];
#pragma unroll 8
    for (int t = 0; t < SEGLEN; ++t) {
        size_t idx = base + (size_t)t * DD;
        float zv = 1.0f / (1.0f + expf(-zl[idx]));
        hc = fmaf(zv, hb[idx] - hc, hc);
        h[idx] = hc;
    }
}

// ---------------------------------------------------------------------------
// Max-abs norm, in place
// ---------------------------------------------------------------------------
__global__ __launch_bounds__(256) void norm_kernel(float* __restrict__ h, int rows) {
    int warp = (blockIdx.x * blockDim.x + threadIdx.x) >> 5;
    int lane = threadIdx.x & 31;
    if (warp >= rows) return;
    float4* row = (float4*)(h + (size_t)warp * DD);
    float4 vals[4];
    float m = 0.0f;
#pragma unroll
    for (int j = 0; j < 4; ++j) {
        vals[j] = row[lane + 32 * j];
        m = fmaxf(m, fmaxf(fmaxf(fabsf(vals[j].x), fabsf(vals[j].y)),
                           fmaxf(fabsf(vals[j].z), fabsf(vals[j].w))));
    }
#pragma unroll
    for (int off = 16; off; off >>= 1)
        m = fmaxf(m, __shfl_xor_sync(0xffffffffu, m, off));
    float inv = 1.0f / (m + 1e-6f);
#pragma unroll
    for (int j = 0; j < 4; ++j) {
        vals[j].x *= inv; vals[j].y *= inv; vals[j].z *= inv; vals[j].w *= inv;
        row[lane + 32 * j] = vals[j];
    }
}

// ---------------------------------------------------------------------------
// kernel_launch (launch #3 = apl_hmma for the ncu capture window)
// ---------------------------------------------------------------------------
extern "C" void kernel_launch(void* const* d_in, const int* in_sizes, int n_in,
                              void* d_out, int out_size) {
    const float* x   = (const float*)d_in[0];
    const float* pz0 = (const float*)d_in[1];
    const float* vz0 = (const float*)d_in[2];
    const float* ph0 = (const float*)d_in[3];
    const float* vh0 = (const float*)d_in[4];
    const float* pz1 = (const float*)d_in[5];
    const float* vz1 = (const float*)d_in[6];
    const float* ph1 = (const float*)d_in[7];
    const float* vh1 = (const float*)d_in[8];
    const float* po  = (const float*)d_in[9];
    const float* vo  = (const float*)d_in[10];

    const int N = in_sizes[0] / DD;  // 16384

    float *s0, *s1, *zl, *hb;
    __half *bhi, *blo;
    cudaGetSymbolAddress((void**)&s0, g_s0);
    cudaGetSymbolAddress((void**)&s1, g_s1);
    cudaGetSymbolAddress((void**)&zl, g_zl);
    cudaGetSymbolAddress((void**)&hb, g_hbar);
    cudaGetSymbolAddress((void**)&bhi, g_bt_hi);
    cudaGetSymbolAddress((void**)&blo, g_bt_lo);

    static int smem_set = 0;
    if (!smem_set) {
        cudaFuncSetAttribute(apl_hmma_kernel,
                             cudaFuncAttributeMaxDynamicSharedMemorySize, SMEM_REQ);
        smem_set = 1;
    }

    float* out = (float*)d_out;
    float* h1  = out + (size_t)N * DD;
    float* h2  = h1 + (size_t)N * DD;

    dim3 tgrid(DD / 32, N / 32);
    dim3 tblk(32, 8);
    dim3 spgrid(64, 4, 5);
    dim3 ggrid(N / 128, DD / 128);
    const int p1_blocks = (BD * SEG * DD + 255) / 256;
    const int p2_blocks = (BD * DD + 255) / 256;
    const int norm_blocks = (N * 32 + 255) / 256;
    const size_t LSZ = (size_t)4 * 64 * 8192;  // halves per layer

    // [1] pre-stage all V into chunked/pre-swizzled fp16 hi/lo tiles
    split_chunk_kernel<<<spgrid, 256>>>(vz0, vh0, vz1, vh1, vo);

    // ---- layer 0 ----
    build_s_kernel<<<tgrid, tblk>>>(x, pz0, s0, N);                                   // [2]
    apl_hmma_kernel<<<ggrid, 512, SMEM_REQ>>>(s0, bhi + 0 * LSZ, blo + 0 * LSZ, zl);  // [3] profiled
    build_s_kernel<<<tgrid, tblk>>>(x, ph0, s1, N);                                   // [4]
    apl_hmma_kernel<<<ggrid, 512, SMEM_REQ>>>(s1, bhi + 1 * LSZ, blo + 1 * LSZ, hb);  // [5]
    scan_p1<<<p1_blocks, 256>>>(zl, hb);
    scan_p2<<<p2_blocks, 256>>>();
    scan_p3<<<p1_blocks, 256>>>(zl, hb, h1);
    norm_kernel<<<norm_blocks, 256>>>(h1, N);

    // ---- layer 1 ----
    build_s_kernel<<<tgrid, tblk>>>(h1, pz1, s0, N);
    apl_hmma_kernel<<<ggrid, 512, SMEM_REQ>>>(s0, bhi + 2 * LSZ, blo + 2 * LSZ, zl);
    build_s_kernel<<<tgrid, tblk>>>(h1, ph1, s1, N);
    apl_hmma_kernel<<<ggrid, 512, SMEM_REQ>>>(s1, bhi + 3 * LSZ, blo + 3 * LSZ, hb);
    scan_p1<<<p1_blocks, 256>>>(zl, hb);
    scan_p2<<<p2_blocks, 256>>>();
    scan_p3<<<p1_blocks, 256>>>(zl, hb, h2);
    norm_kernel<<<norm_blocks, 256>>>(h2, N);

    // ---- output APL ----
    build_s_kernel<<<tgrid, tblk>>>(h2, po, s0, N);
    apl_hmma_kernel<<<ggrid, 512, SMEM_REQ>>>(s0, bhi + 4 * LSZ, blo + 4 * LSZ, out);
}

// round 8
// speedup vs baseline: 4.0587x; 1.0737x over previous
#include <cuda_runtime.h>
#include <cuda_fp16.h>
#include <math.h>
#include <stdint.h>

// Problem constants
#define BD   8
#define TD   2048
#define DD   512
#define NTOT (BD * TD)     // 16384
#define KTOT 4096          // D * P
#define NKC  64            // K-chunks of 64 elements
#define SEG  16
#define SEGLEN (TD / SEG)  // 128

// ---------------------------------------------------------------------------
// Scratch (device globals — no allocations allowed)
// ---------------------------------------------------------------------------
__device__ float g_s0[(size_t)DD * NTOT];
__device__ float g_s1[(size_t)DD * NTOT];
__device__ float g_zl[(size_t)NTOT * DD];
__device__ float g_hbar[(size_t)NTOT * DD];
// Pre-swizzled chunk tiles: [layer][nb(4)][kc(64)] each 16KB (128 rows x 64 cols fp16)
__device__ __half g_bt_hi[5][(size_t)4 * 64 * 8192];
__device__ __half g_bt_lo[5][(size_t)4 * 64 * 8192];
// scan scratch
__device__ float g_scanA[BD * SEG * DD];
__device__ float g_scanB[BD * SEG * DD];
__device__ float g_scanH[BD * SEG * DD];

// ---------------------------------------------------------------------------
// helpers
// ---------------------------------------------------------------------------
__device__ __forceinline__ uint32_t smem_u32(const void* p) {
    uint32_t a;
    asm("{ .reg .u64 t; cvta.to.shared.u64 t, %1; cvt.u32.u64 %0, t; }"
        : "=r"(a) : "l"(p));
    return a;
}

#define SWZ(x) ((x) ^ (((x) >> 3) & 0x70))

__device__ __forceinline__ void mbar_init(uint32_t a, uint32_t cnt) {
    asm volatile("mbarrier.init.shared.b64 [%0], %1;" :: "r"(a), "r"(cnt) : "memory");
}

__device__ __forceinline__ void mbar_wait(uint32_t a, uint32_t ph) {
    asm volatile(
        "{\n\t.reg .pred P;\n\t"
        "W%=:\n\t"
        "mbarrier.try_wait.parity.acquire.cta.shared::cta.b64 P, [%0], %1, 0x989680;\n\t"
        "@P bra.uni D%=;\n\t"
        "bra.uni W%=;\n\t"
        "D%=:\n\t}"
        :: "r"(a), "r"(ph) : "memory");
}

__device__ __forceinline__ void mbar_expect_tx(uint32_t a, uint32_t bytes) {
    asm volatile("mbarrier.arrive.expect_tx.shared.b64 _, [%0], %1;"
                 :: "r"(a), "r"(bytes) : "memory");
}

__device__ __forceinline__ void bulk_ld(uint32_t dst, const void* src,
                                        uint32_t bytes, uint32_t mbar) {
    asm volatile(
        "cp.async.bulk.shared::cluster.global.mbarrier::complete_tx::bytes "
        "[%0], [%1], %2, [%3];"
        :: "r"(dst), "l"(src), "r"(bytes), "r"(mbar) : "memory");
}

// ---------------------------------------------------------------------------
// build_s (paired via blockIdx.z): s[i*N+n] = k + t
// ---------------------------------------------------------------------------
__global__ __launch_bounds__(256) void build_s_pair_kernel(
    const float* __restrict__ X, const float* __restrict__ P0,
    const float* __restrict__ P1, float* __restrict__ S0,
    float* __restrict__ S1, int N) {
    const float* Pp = blockIdx.z ? P1 : P0;
    float* S = blockIdx.z ? S1 : S0;
    __shared__ float tile[32][33];
    int i0 = blockIdx.x * 32;
    int n0 = blockIdx.y * 32;
    int tx = threadIdx.x;
    int ty = threadIdx.y;
    int i = i0 + tx;

    float p[8];
#pragma unroll
    for (int j = 0; j < 8; ++j) p[j] = Pp[i * 8 + j];

#pragma unroll
    for (int r = 0; r < 4; ++r) {
        int nl = ty + 8 * r;
        int n = n0 + nl;
        float x = X[(size_t)n * DD + i];
        int k = 0;
        float pl = p[0], pr = p[1];
#pragma unroll
        for (int j = 1; j <= 6; ++j) {
            if (p[j] < x) { k = j; pl = p[j]; pr = p[j + 1]; }
        }
        float t = (x - pl) / (pr - pl);
        t = fminf(fmaxf(t, 0.0f), 1.0f);
        tile[nl][tx] = (float)k + t;
    }
    __syncthreads();
#pragma unroll
    for (int r = 0; r < 4; ++r) {
        int il = ty + 8 * r;
        S[(size_t)(i0 + il) * N + n0 + tx] = tile[tx][il];
    }
}

// ---------------------------------------------------------------------------
// split_chunk: v (4096 x 512 f32) -> pre-swizzled 16KB chunk tiles, fp16 hi/lo.
// ---------------------------------------------------------------------------
__global__ __launch_bounds__(256) void split_chunk_kernel(
    const float* __restrict__ v0, const float* __restrict__ v1,
    const float* __restrict__ v2, const float* __restrict__ v3,
    const float* __restrict__ v4) {
    int kc = blockIdx.x, nb = blockIdx.y, layer = blockIdx.z;
    const float* v = (layer == 0) ? v0 : (layer == 1) ? v1 :
                     (layer == 2) ? v2 : (layer == 3) ? v3 : v4;
    size_t tile_off = ((size_t)layer * 256 + nb * 64 + kc) << 14;  // bytes
    char* hib = (char*)g_bt_hi + tile_off;
    char* lob = (char*)g_bt_lo + tile_off;

    int r = threadIdx.x & 127;
    int chalf = threadIdx.x >> 7;
#pragma unroll
    for (int j = 0; j < 32; ++j) {
        int c = chalf * 32 + j;
        float val = v[(size_t)(kc * 64 + c) * DD + nb * 128 + r];
        __half h = __float2half_rn(val);
        float res = val - __half2float(h);
        uint32_t off = SWZ((uint32_t)(r * 128 + c * 2));
        *(__half*)(hib + off) = h;
        *(__half*)(lob + off) = __float2half_rn(res);
    }
}

// ---------------------------------------------------------------------------
// APL HMMA GEMM, fp16 2-term split, B via cp.async.bulk.
// 256 threads, 8 warps (2Mx4N), warp tile 64x32, CTA tile 128x128.
// Paired: blockIdx.z selects (S, B, out) set.
// ---------------------------------------------------------------------------
#define TILE16K 16384
#define SMEM_REQ (1024 + 2 * TILE16K + 6 * TILE16K)

__device__ __forceinline__ void build_A(const float* __restrict__ S, int bm,
                                        int kc, uint32_t ahi, int tid) {
#pragma unroll
    for (int q = 0; q < 4; ++q) {
        int idx = tid + 256 * q;
        int n = idx & 127;
        int il = idx >> 7;
        float sv = __ldg(&S[(size_t)(kc * 8 + il) * NTOT + bm + n]);
        int k = min((int)sv, 6);
        float t = sv - (float)k;
        __half2 h2 = __floats2half2_rn(1.0f - t, t);
        uint32_t Phi = *(uint32_t*)&h2;
        int j = k >> 1;
        int odd = k & 1;
        uint32_t e = odd ? (Phi << 16) : Phi;
        uint32_t sft = odd ? (Phi >> 16) : 0u;
        uint32_t w[4];
#pragma unroll
        for (int m = 0; m < 4; ++m)
            w[m] = (m == j) ? e : ((m == j + 1) ? sft : 0u);
        uint32_t off = SWZ((uint32_t)(n * 128 + il * 16));
        asm volatile("st.shared.v4.b32 [%0], {%1,%2,%3,%4};"
                     :: "r"(ahi + off), "r"(w[0]), "r"(w[1]), "r"(w[2]), "r"(w[3])
                     : "memory");
    }
}

__device__ __forceinline__ void ldsm4(uint32_t a, uint32_t& r0, uint32_t& r1,
                                      uint32_t& r2, uint32_t& r3) {
    asm volatile("ldmatrix.sync.aligned.m8n8.x4.shared.b16 {%0,%1,%2,%3}, [%4];"
                 : "=r"(r0), "=r"(r1), "=r"(r2), "=r"(r3) : "r"(a));
}

__device__ __forceinline__ void mma16816(float* d, const uint32_t* a,
                                         const uint32_t* b) {
    asm volatile(
        "mma.sync.aligned.m16n8k16.row.col.f32.f16.f16.f32 "
        "{%0,%1,%2,%3}, {%4,%5,%6,%7}, {%8,%9}, {%0,%1,%2,%3};"
        : "+f"(d[0]), "+f"(d[1]), "+f"(d[2]), "+f"(d[3])
        : "r"(a[0]), "r"(a[1]), "r"(a[2]), "r"(a[3]), "r"(b[0]), "r"(b[1]));
}

__global__ void __launch_bounds__(256, 1) apl_hmma_kernel(
    const float* __restrict__ S0, const float* __restrict__ S1,
    const __half* __restrict__ Bhi0, const __half* __restrict__ Blo0,
    const __half* __restrict__ Bhi1, const __half* __restrict__ Blo1,
    float* __restrict__ out0, float* __restrict__ out1) {
    const int zz = blockIdx.z;
    const float* S = zz ? S1 : S0;
    const __half* Bhi = zz ? Bhi1 : Bhi0;
    const __half* Blo = zz ? Blo1 : Blo0;
    float* out = zz ? out1 : out0;

    extern __shared__ char smem[];
    uint32_t sb = (smem_u32(smem) + 1023u) & ~1023u;
    const uint32_t MB = sb;
    const uint32_t AH = sb + 1024;
    const uint32_t BH = AH + 2 * TILE16K;
    const uint32_t BL = BH + 3 * TILE16K;
    const int tid = threadIdx.x;
    const int lane = tid & 31;
    const int wid = tid >> 5;
    const int wm = wid & 1;             // 2 warp rows (64 each)
    const int wn = wid >> 1;            // 4 warp cols (32 each)
    const int bm = blockIdx.x * 128;
    const int nb = blockIdx.y;

    const char* hsrc = (const char*)Bhi + ((size_t)nb * 64 << 14);
    const char* lsrc = (const char*)Blo + ((size_t)nb * 64 << 14);

    if (tid == 0) {
        mbar_init(MB + 0, 1);
        mbar_init(MB + 8, 1);
        mbar_init(MB + 16, 1);
        asm volatile("fence.proxy.async.shared::cta;" ::: "memory");
    }
    __syncthreads();

    float acc[4][4][4];
#pragma unroll
    for (int mi = 0; mi < 4; ++mi)
#pragma unroll
        for (int nj = 0; nj < 4; ++nj)
#pragma unroll
            for (int u = 0; u < 4; ++u) acc[mi][nj][u] = 0.0f;

    uint32_t a_off[4], b_off[2];
#pragma unroll
    for (int mi = 0; mi < 4; ++mi) {
        int row = wm * 64 + mi * 16 + (lane & 15);
        a_off[mi] = (uint32_t)(row * 128 + (lane >> 4) * 16);
    }
#pragma unroll
    for (int ni = 0; ni < 2; ++ni) {
        int row = wn * 32 + ni * 16 + (lane & 7) + ((lane & 16) >> 1);
        b_off[ni] = (uint32_t)(row * 128 + ((lane >> 3) & 1) * 16);
    }

    if (tid == 0) {
#pragma unroll
        for (int c = 0; c < 2; ++c) {
            mbar_expect_tx(MB + c * 8, 2 * TILE16K);
            bulk_ld(BH + c * TILE16K, hsrc + ((size_t)c << 14), TILE16K, MB + c * 8);
            bulk_ld(BL + c * TILE16K, lsrc + ((size_t)c << 14), TILE16K, MB + c * 8);
        }
    }
    build_A(S, bm, 0, AH, tid);

    for (int kc = 0; kc < NKC; ++kc) {
        int st = kc % 3;
        uint32_t parity = (uint32_t)((kc / 3) & 1);
        mbar_wait(MB + st * 8, parity);
        __syncthreads();

        if (tid == 0 && kc + 2 < NKC) {
            int s2 = (kc + 2) % 3;
            mbar_expect_tx(MB + s2 * 8, 2 * TILE16K);
            bulk_ld(BH + s2 * TILE16K, hsrc + ((size_t)(kc + 2) << 14), TILE16K, MB + s2 * 8);
            bulk_ld(BL + s2 * TILE16K, lsrc + ((size_t)(kc + 2) << 14), TILE16K, MB + s2 * 8);
        }

        const uint32_t AHc = AH + (kc & 1) * TILE16K;
        const uint32_t BHc = BH + st * TILE16K;
        const uint32_t BLc = BL + st * TILE16K;

#pragma unroll
        for (int kk = 0; kk < 4; ++kk) {
            uint32_t ah[4][4], bh[4][2], bl_[4][2];
#pragma unroll
            for (int mi = 0; mi < 4; ++mi)
                ldsm4(AHc + SWZ(a_off[mi] + kk * 32),
                      ah[mi][0], ah[mi][1], ah[mi][2], ah[mi][3]);
#pragma unroll
            for (int ni = 0; ni < 2; ++ni) {
                uint32_t r0, r1, r2, r3;
                ldsm4(BHc + SWZ(b_off[ni] + kk * 32), r0, r1, r2, r3);
                bh[2 * ni][0] = r0; bh[2 * ni][1] = r1;
                bh[2 * ni + 1][0] = r2; bh[2 * ni + 1][1] = r3;
            }
#pragma unroll
            for (int mi = 0; mi < 4; ++mi)
#pragma unroll
                for (int nj = 0; nj < 4; ++nj)
                    mma16816(acc[mi][nj], ah[mi], bh[nj]);   // A_hi x B_hi

#pragma unroll
            for (int ni = 0; ni < 2; ++ni) {
                uint32_t r0, r1, r2, r3;
                ldsm4(BLc + SWZ(b_off[ni] + kk * 32), r0, r1, r2, r3);
                bl_[2 * ni][0] = r0; bl_[2 * ni][1] = r1;
                bl_[2 * ni + 1][0] = r2; bl_[2 * ni + 1][1] = r3;
            }
#pragma unroll
            for (int mi = 0; mi < 4; ++mi)
#pragma unroll
                for (int nj = 0; nj < 4; ++nj)
                    mma16816(acc[mi][nj], ah[mi], bl_[nj]);  // A_hi x B_lo
        }

        if (kc + 1 < NKC)
            build_A(S, bm, kc + 1, AH + ((kc + 1) & 1) * TILE16K, tid);
    }

    // epilogue
#pragma unroll
    for (int mi = 0; mi < 4; ++mi) {
#pragma unroll
        for (int nj = 0; nj < 4; ++nj) {
            int row = bm + wm * 64 + mi * 16 + (lane >> 2);
            int col = nb * 128 + wn * 32 + nj * 8 + 2 * (lane & 3);
            float2* p0 = (float2*)&out[(size_t)row * DD + col];
            float2* p1 = (float2*)&out[(size_t)(row + 8) * DD + col];
            *p0 = make_float2(acc[mi][nj][0], acc[mi][nj][1]);
            *p1 = make_float2(acc[mi][nj][2], acc[mi][nj][3]);
        }
    }
}

// ---------------------------------------------------------------------------
// Segmented scan (3 passes)
// ---------------------------------------------------------------------------
__global__ __launch_bounds__(256) void scan_p1(
    const float* __restrict__ zl, const float* __restrict__ hb) {
    int gid = blockIdx.x * blockDim.x + threadIdx.x;
    if (gid >= BD * SEG * DD) return;
    int d = gid & 511;
    int bs = gid >> 9;
    int seg = bs & (SEG - 1);
    int b = bs / SEG;
    size_t base = (size_t)b * TD * DD + (size_t)seg * SEGLEN * DD + d;
    float A = 1.0f, Bv = 0.0f;
#pragma unroll 8
    for (int t = 0; t < SEGLEN; ++t) {
        size_t idx = base + (size_t)t * DD;
        float zv = 1.0f / (1.0f + expf(-zl[idx]));
        float a = 1.0f - zv;
        float bb = zv * hb[idx];
        A *= a;
        Bv = fmaf(a, Bv, bb);
    }
    g_scanA[gid] = A;
    g_scanB[gid] = Bv;
}

__global__ __launch_bounds__(256) void scan_p2() {
    int c = blockIdx.x * blockDim.x + threadIdx.x;
    if (c >= BD * DD) return;
    int d = c & 511;
    int b = c >> 9;
    float h = 0.0f;
#pragma unroll
    for (int seg = 0; seg < SEG; ++seg) {
        int gid = ((b * SEG + seg) << 9) + d;
        g_scanH[gid] = h;
        h = fmaf(g_scanA[gid], h, g_scanB[gid]);
    }
}

__global__ __launch_bounds__(256) void scan_p3(
    const float* __restrict__ zl, const float* __restrict__ hb,
    float* __restrict__ h) {
    int gid = blockIdx.x * blockDim.x + threadIdx.x;
    if (gid >= BD * SEG * DD) return;
    int d = gid & 511;
    int bs = gid >> 9;
    int seg = bs & (SEG - 1);
    int b = bs / SEG;
    size_t base = (size_t)b * TD * DD + (size_t)seg * SEGLEN * DD + d;
    float hc = g_scanH[gid];
#pragma unroll 8
    for (int t = 0; t < SEGLEN; ++t) {
        size_t idx = base + (size_t)t * DD;
        float zv = 1.0f / (1.0f + expf(-zl[idx]));
        hc = fmaf(zv, hb[idx] - hc, hc);
        h[idx] = hc;
    }
}

// ---------------------------------------------------------------------------
// Max-abs norm, in place
// ---------------------------------------------------------------------------
__global__ __launch_bounds__(256) void norm_kernel(float* __restrict__ h, int rows) {
    int warp = (blockIdx.x * blockDim.x + threadIdx.x) >> 5;
    int lane = threadIdx.x & 31;
    if (warp >= rows) return;
    float4* row = (float4*)(h + (size_t)warp * DD);
    float4 vals[4];
    float m = 0.0f;
#pragma unroll
    for (int j = 0; j < 4; ++j) {
        vals[j] = row[lane + 32 * j];
        m = fmaxf(m, fmaxf(fmaxf(fabsf(vals[j].x), fabsf(vals[j].y)),
                           fmaxf(fabsf(vals[j].z), fabsf(vals[j].w))));
    }
#pragma unroll
    for (int off = 16; off; off >>= 1)
        m = fmaxf(m, __shfl_xor_sync(0xffffffffu, m, off));
    float inv = 1.0f / (m + 1e-6f);
#pragma unroll
    for (int j = 0; j < 4; ++j) {
        vals[j].x *= inv; vals[j].y *= inv; vals[j].z *= inv; vals[j].w *= inv;
        row[lane + 32 * j] = vals[j];
    }
}

// ---------------------------------------------------------------------------
// kernel_launch (launch #3 = paired apl_hmma for the ncu capture window)
// ---------------------------------------------------------------------------
extern "C" void kernel_launch(void* const* d_in, const int* in_sizes, int n_in,
                              void* d_out, int out_size) {
    const float* x   = (const float*)d_in[0];
    const float* pz0 = (const float*)d_in[1];
    const float* vz0 = (const float*)d_in[2];
    const float* ph0 = (const float*)d_in[3];
    const float* vh0 = (const float*)d_in[4];
    const float* pz1 = (const float*)d_in[5];
    const float* vz1 = (const float*)d_in[6];
    const float* ph1 = (const float*)d_in[7];
    const float* vh1 = (const float*)d_in[8];
    const float* po  = (const float*)d_in[9];
    const float* vo  = (const float*)d_in[10];

    const int N = in_sizes[0] / DD;  // 16384

    float *s0, *s1, *zl, *hb;
    __half *bhi, *blo;
    cudaGetSymbolAddress((void**)&s0, g_s0);
    cudaGetSymbolAddress((void**)&s1, g_s1);
    cudaGetSymbolAddress((void**)&zl, g_zl);
    cudaGetSymbolAddress((void**)&hb, g_hbar);
    cudaGetSymbolAddress((void**)&bhi, g_bt_hi);
    cudaGetSymbolAddress((void**)&blo, g_bt_lo);

    static int smem_set = 0;
    if (!smem_set) {
        cudaFuncSetAttribute(apl_hmma_kernel,
                             cudaFuncAttributeMaxDynamicSharedMemorySize, SMEM_REQ);
        smem_set = 1;
    }

    float* out = (float*)d_out;
    float* h1  = out + (size_t)N * DD;
    float* h2  = h1 + (size_t)N * DD;

    dim3 tgrid(DD / 32, N / 32, 2);
    dim3 tblk(32, 8);
    dim3 spgrid(64, 4, 5);
    dim3 gpair(N / 128, DD / 128, 2);
    dim3 gone(N / 128, DD / 128, 1);
    const int p1_blocks = (BD * SEG * DD + 255) / 256;
    const int p2_blocks = (BD * DD + 255) / 256;
    const int norm_blocks = (N * 32 + 255) / 256;
    const size_t LSZ = (size_t)4 * 64 * 8192;

    // [1] pre-stage all V into chunked/pre-swizzled fp16 hi/lo tiles
    split_chunk_kernel<<<spgrid, 256>>>(vz0, vh0, vz1, vh1, vo);

    // ---- layer 0 ----
    build_s_pair_kernel<<<tgrid, tblk>>>(x, pz0, ph0, s0, s1, N);            // [2]
    apl_hmma_kernel<<<gpair, 256, SMEM_REQ>>>(s0, s1, bhi + 0 * LSZ, blo + 0 * LSZ,
                                              bhi + 1 * LSZ, blo + 1 * LSZ, zl, hb);  // [3] profiled
    scan_p1<<<p1_blocks, 256>>>(zl, hb);
    scan_p2<<<p2_blocks, 256>>>();
    scan_p3<<<p1_blocks, 256>>>(zl, hb, h1);
    norm_kernel<<<norm_blocks, 256>>>(h1, N);

    // ---- layer 1 ----
    build_s_pair_kernel<<<tgrid, tblk>>>(h1, pz1, ph1, s0, s1, N);
    apl_hmma_kernel<<<gpair, 256, SMEM_REQ>>>(s0, s1, bhi + 2 * LSZ, blo + 2 * LSZ,
                                              bhi + 3 * LSZ, blo + 3 * LSZ, zl, hb);
    scan_p1<<<p1_blocks, 256>>>(zl, hb);
    scan_p2<<<p2_blocks, 256>>>();
    scan_p3<<<p1_blocks, 256>>>(zl, hb, h2);
    norm_kernel<<<norm_blocks, 256>>>(h2, N);

    // ---- output APL ----
    build_s_pair_kernel<<<dim3(DD / 32, N / 32, 1), tblk>>>(h2, po, po, s0, s1, N);
    apl_hmma_kernel<<<gone, 256, SMEM_REQ>>>(s0, s0, bhi + 4 * LSZ, blo + 4 * LSZ,
                                             bhi + 4 * LSZ, blo + 4 * LSZ, out, out);
}

// round 9
// speedup vs baseline: 8.0090x; 1.9733x over previous
#include <cuda_runtime.h>
#include <cuda_fp16.h>
#include <math.h>
#include <stdint.h>

// Problem constants
#define BD   8
#define TD   2048
#define DD   512
#define NTOT (BD * TD)     // 16384
#define KTOT 4096          // D * P
#define NKC  64            // K-chunks of 64 elements
#define SEG  64
#define SEGLEN (TD / SEG)  // 32

// ---------------------------------------------------------------------------
// Scratch (device globals — no allocations allowed)
// ---------------------------------------------------------------------------
__device__ float g_s0[(size_t)DD * NTOT];
__device__ float g_s1[(size_t)DD * NTOT];
__device__ float g_zl[(size_t)NTOT * DD];
__device__ float g_hbar[(size_t)NTOT * DD];
// Pre-swizzled chunk tiles: [layer][nb(4)][kc(64)] each 16KB (128 rows x 64 cols fp16)
__device__ __half g_bt_hi[5][(size_t)4 * 64 * 8192];
// scan scratch
__device__ float g_scanA[BD * SEG * DD];
__device__ float g_scanB[BD * SEG * DD];
__device__ float g_scanH[BD * SEG * DD];

// ---------------------------------------------------------------------------
// helpers
// ---------------------------------------------------------------------------
__device__ __forceinline__ uint32_t smem_u32(const void* p) {
    uint32_t a;
    asm("{ .reg .u64 t; cvta.to.shared.u64 t, %1; cvt.u32.u64 %0, t; }"
        : "=r"(a) : "l"(p));
    return a;
}

#define SWZ(x) ((x) ^ (((x) >> 3) & 0x70))

__device__ __forceinline__ void mbar_init(uint32_t a, uint32_t cnt) {
    asm volatile("mbarrier.init.shared.b64 [%0], %1;" :: "r"(a), "r"(cnt) : "memory");
}

__device__ __forceinline__ void mbar_wait(uint32_t a, uint32_t ph) {
    asm volatile(
        "{\n\t.reg .pred P;\n\t"
        "W%=:\n\t"
        "mbarrier.try_wait.parity.acquire.cta.shared::cta.b64 P, [%0], %1, 0x989680;\n\t"
        "@P bra.uni D%=;\n\t"
        "bra.uni W%=;\n\t"
        "D%=:\n\t}"
        :: "r"(a), "r"(ph) : "memory");
}

__device__ __forceinline__ void mbar_expect_tx(uint32_t a, uint32_t bytes) {
    asm volatile("mbarrier.arrive.expect_tx.shared.b64 _, [%0], %1;"
                 :: "r"(a), "r"(bytes) : "memory");
}

__device__ __forceinline__ void bulk_ld(uint32_t dst, const void* src,
                                        uint32_t bytes, uint32_t mbar) {
    asm volatile(
        "cp.async.bulk.shared::cluster.global.mbarrier::complete_tx::bytes "
        "[%0], [%1], %2, [%3];"
        :: "r"(dst), "l"(src), "r"(bytes), "r"(mbar) : "memory");
}

// ---------------------------------------------------------------------------
// build_s (paired via blockIdx.z): s[i*N+n] = k + t
// ---------------------------------------------------------------------------
__global__ __launch_bounds__(256) void build_s_pair_kernel(
    const float* __restrict__ X, const float* __restrict__ P0,
    const float* __restrict__ P1, float* __restrict__ S0,
    float* __restrict__ S1, int N) {
    const float* Pp = blockIdx.z ? P1 : P0;
    float* S = blockIdx.z ? S1 : S0;
    __shared__ float tile[32][33];
    int i0 = blockIdx.x * 32;
    int n0 = blockIdx.y * 32;
    int tx = threadIdx.x;
    int ty = threadIdx.y;
    int i = i0 + tx;

    float p[8];
#pragma unroll
    for (int j = 0; j < 8; ++j) p[j] = Pp[i * 8 + j];

#pragma unroll
    for (int r = 0; r < 4; ++r) {
        int nl = ty + 8 * r;
        int n = n0 + nl;
        float x = X[(size_t)n * DD + i];
        int k = 0;
        float pl = p[0], pr = p[1];
#pragma unroll
        for (int j = 1; j <= 6; ++j) {
            if (p[j] < x) { k = j; pl = p[j]; pr = p[j + 1]; }
        }
        float t = (x - pl) / (pr - pl);
        t = fminf(fmaxf(t, 0.0f), 1.0f);
        tile[nl][tx] = (float)k + t;
    }
    __syncthreads();
#pragma unroll
    for (int r = 0; r < 4; ++r) {
        int il = ty + 8 * r;
        S[(size_t)(i0 + il) * N + n0 + tx] = tile[tx][il];
    }
}

// ---------------------------------------------------------------------------
// split_chunk: v (4096 x 512 f32) -> pre-swizzled 16KB chunk tiles, fp16 hi.
// ---------------------------------------------------------------------------
__global__ __launch_bounds__(256) void split_chunk_kernel(
    const float* __restrict__ v0, const float* __restrict__ v1,
    const float* __restrict__ v2, const float* __restrict__ v3,
    const float* __restrict__ v4) {
    int kc = blockIdx.x, nb = blockIdx.y, layer = blockIdx.z;
    const float* v = (layer == 0) ? v0 : (layer == 1) ? v1 :
                     (layer == 2) ? v2 : (layer == 3) ? v3 : v4;
    size_t tile_off = ((size_t)layer * 256 + nb * 64 + kc) << 14;  // bytes
    char* hib = (char*)g_bt_hi + tile_off;

    int r = threadIdx.x & 127;
    int chalf = threadIdx.x >> 7;
#pragma unroll
    for (int j = 0; j < 32; ++j) {
        int c = chalf * 32 + j;
        float val = v[(size_t)(kc * 64 + c) * DD + nb * 128 + r];
        uint32_t off = SWZ((uint32_t)(r * 128 + c * 2));
        *(__half*)(hib + off) = __float2half_rn(val);
    }
}

// ---------------------------------------------------------------------------
// APL HMMA GEMM, single fp16 term, B via cp.async.bulk.
// 256 threads, 8 warps (2Mx4N), warp tile 64x32, CTA tile 128x128, 2 CTA/SM.
// Paired: blockIdx.z selects (S, B, out) set.
// ---------------------------------------------------------------------------
#define TILE16K 16384
#define SMEM_REQ (1024 + 2 * TILE16K + 3 * TILE16K)

__device__ __forceinline__ void build_A(const float* __restrict__ S, int bm,
                                        int kc, uint32_t ahi, int tid) {
#pragma unroll
    for (int q = 0; q < 4; ++q) {
        int idx = tid + 256 * q;
        int n = idx & 127;
        int il = idx >> 7;
        float sv = __ldg(&S[(size_t)(kc * 8 + il) * NTOT + bm + n]);
        int k = min((int)sv, 6);
        float t = sv - (float)k;
        __half2 h2 = __floats2half2_rn(1.0f - t, t);
        uint32_t Phi = *(uint32_t*)&h2;
        int j = k >> 1;
        int odd = k & 1;
        uint32_t e = odd ? (Phi << 16) : Phi;
        uint32_t sft = odd ? (Phi >> 16) : 0u;
        uint32_t w[4];
#pragma unroll
        for (int m = 0; m < 4; ++m)
            w[m] = (m == j) ? e : ((m == j + 1) ? sft : 0u);
        uint32_t off = SWZ((uint32_t)(n * 128 + il * 16));
        asm volatile("st.shared.v4.b32 [%0], {%1,%2,%3,%4};"
                     :: "r"(ahi + off), "r"(w[0]), "r"(w[1]), "r"(w[2]), "r"(w[3])
                     : "memory");
    }
}

__device__ __forceinline__ void ldsm4(uint32_t a, uint32_t& r0, uint32_t& r1,
                                      uint32_t& r2, uint32_t& r3) {
    asm volatile("ldmatrix.sync.aligned.m8n8.x4.shared.b16 {%0,%1,%2,%3}, [%4];"
                 : "=r"(r0), "=r"(r1), "=r"(r2), "=r"(r3) : "r"(a));
}

__device__ __forceinline__ void mma16816(float* d, const uint32_t* a,
                                         const uint32_t* b) {
    asm volatile(
        "mma.sync.aligned.m16n8k16.row.col.f32.f16.f16.f32 "
        "{%0,%1,%2,%3}, {%4,%5,%6,%7}, {%8,%9}, {%0,%1,%2,%3};"
        : "+f"(d[0]), "+f"(d[1]), "+f"(d[2]), "+f"(d[3])
        : "r"(a[0]), "r"(a[1]), "r"(a[2]), "r"(a[3]), "r"(b[0]), "r"(b[1]));
}

__global__ void __launch_bounds__(256, 2) apl_hmma_kernel(
    const float* __restrict__ S0, const float* __restrict__ S1,
    const __half* __restrict__ Bhi0, const __half* __restrict__ Bhi1,
    float* __restrict__ out0, float* __restrict__ out1) {
    const int zz = blockIdx.z;
    const float* S = zz ? S1 : S0;
    const __half* Bhi = zz ? Bhi1 : Bhi0;
    float* out = zz ? out1 : out0;

    extern __shared__ char smem[];
    uint32_t sb = (smem_u32(smem) + 1023u) & ~1023u;
    const uint32_t MB = sb;
    const uint32_t AH = sb + 1024;
    const uint32_t BH = AH + 2 * TILE16K;
    const int tid = threadIdx.x;
    const int lane = tid & 31;
    const int wid = tid >> 5;
    const int wm = wid & 1;             // 2 warp rows (64 each)
    const int wn = wid >> 1;            // 4 warp cols (32 each)
    const int bm = blockIdx.x * 128;
    const int nb = blockIdx.y;

    const char* hsrc = (const char*)Bhi + ((size_t)nb * 64 << 14);

    if (tid == 0) {
        mbar_init(MB + 0, 1);
        mbar_init(MB + 8, 1);
        mbar_init(MB + 16, 1);
        asm volatile("fence.proxy.async.shared::cta;" ::: "memory");
    }
    __syncthreads();

    float acc[4][4][4];
#pragma unroll
    for (int mi = 0; mi < 4; ++mi)
#pragma unroll
        for (int nj = 0; nj < 4; ++nj)
#pragma unroll
            for (int u = 0; u < 4; ++u) acc[mi][nj][u] = 0.0f;

    uint32_t a_off[4], b_off[2];
#pragma unroll
    for (int mi = 0; mi < 4; ++mi) {
        int row = wm * 64 + mi * 16 + (lane & 15);
        a_off[mi] = (uint32_t)(row * 128 + (lane >> 4) * 16);
    }
#pragma unroll
    for (int ni = 0; ni < 2; ++ni) {
        int row = wn * 32 + ni * 16 + (lane & 7) + ((lane & 16) >> 1);
        b_off[ni] = (uint32_t)(row * 128 + ((lane >> 3) & 1) * 16);
    }

    if (tid == 0) {
#pragma unroll
        for (int c = 0; c < 2; ++c) {
            mbar_expect_tx(MB + c * 8, TILE16K);
            bulk_ld(BH + c * TILE16K, hsrc + ((size_t)c << 14), TILE16K, MB + c * 8);
        }
    }
    build_A(S, bm, 0, AH, tid);

    for (int kc = 0; kc < NKC; ++kc) {
        int st = kc % 3;
        uint32_t parity = (uint32_t)((kc / 3) & 1);
        mbar_wait(MB + st * 8, parity);
        __syncthreads();

        if (tid == 0 && kc + 2 < NKC) {
            int s2 = (kc + 2) % 3;
            mbar_expect_tx(MB + s2 * 8, TILE16K);
            bulk_ld(BH + s2 * TILE16K, hsrc + ((size_t)(kc + 2) << 14), TILE16K, MB + s2 * 8);
        }

        const uint32_t AHc = AH + (kc & 1) * TILE16K;
        const uint32_t BHc = BH + st * TILE16K;

#pragma unroll
        for (int kk = 0; kk < 4; ++kk) {
            uint32_t ah[4][4], bh[4][2];
#pragma unroll
            for (int mi = 0; mi < 4; ++mi)
                ldsm4(AHc + SWZ(a_off[mi] + kk * 32),
                      ah[mi][0], ah[mi][1], ah[mi][2], ah[mi][3]);
#pragma unroll
            for (int ni = 0; ni < 2; ++ni) {
                uint32_t r0, r1, r2, r3;
                ldsm4(BHc + SWZ(b_off[ni] + kk * 32), r0, r1, r2, r3);
                bh[2 * ni][0] = r0; bh[2 * ni][1] = r1;
                bh[2 * ni + 1][0] = r2; bh[2 * ni + 1][1] = r3;
            }
#pragma unroll
            for (int mi = 0; mi < 4; ++mi)
#pragma unroll
                for (int nj = 0; nj < 4; ++nj)
                    mma16816(acc[mi][nj], ah[mi], bh[nj]);
        }

        if (kc + 1 < NKC)
            build_A(S, bm, kc + 1, AH + ((kc + 1) & 1) * TILE16K, tid);
    }

    // epilogue
#pragma unroll
    for (int mi = 0; mi < 4; ++mi) {
#pragma unroll
        for (int nj = 0; nj < 4; ++nj) {
            int row = bm + wm * 64 + mi * 16 + (lane >> 2);
            int col = nb * 128 + wn * 32 + nj * 8 + 2 * (lane & 3);
            float2* p0 = (float2*)&out[(size_t)row * DD + col];
            float2* p1 = (float2*)&out[(size_t)(row + 8) * DD + col];
            *p0 = make_float2(acc[mi][nj][0], acc[mi][nj][1]);
            *p1 = make_float2(acc[mi][nj][2], acc[mi][nj][3]);
        }
    }
}

// ---------------------------------------------------------------------------
// Segmented scan (3 passes), SEG=64 for occupancy
// ---------------------------------------------------------------------------
__global__ __launch_bounds__(256) void scan_p1(
    const float* __restrict__ zl, const float* __restrict__ hb) {
    int gid = blockIdx.x * blockDim.x + threadIdx.x;
    if (gid >= BD * SEG * DD) return;
    int d = gid & 511;
    int bs = gid >> 9;
    int seg = bs & (SEG - 1);
    int b = bs / SEG;
    size_t base = (size_t)b * TD * DD + (size_t)seg * SEGLEN * DD + d;
    float A = 1.0f, Bv = 0.0f;
#pragma unroll 8
    for (int t = 0; t < SEGLEN; ++t) {
        size_t idx = base + (size_t)t * DD;
        float zv = 1.0f / (1.0f + expf(-zl[idx]));
        float a = 1.0f - zv;
        float bb = zv * hb[idx];
        A *= a;
        Bv = fmaf(a, Bv, bb);
    }
    g_scanA[gid] = A;
    g_scanB[gid] = Bv;
}

__global__ __launch_bounds__(256) void scan_p2() {
    int c = blockIdx.x * blockDim.x + threadIdx.x;
    if (c >= BD * DD) return;
    int d = c & 511;
    int b = c >> 9;
    float h = 0.0f;
#pragma unroll
    for (int seg = 0; seg < SEG; ++seg) {
        int gid = ((b * SEG + seg) << 9) + d;
        g_scanH[gid] = h;
        h = fmaf(g_scanA[gid], h, g_scanB[gid]);
    }
}

__global__ __launch_bounds__(256) void scan_p3(
    const float* __restrict__ zl, const float* __restrict__ hb,
    float* __restrict__ h) {
    int gid = blockIdx.x * blockDim.x + threadIdx.x;
    if (gid >= BD * SEG * DD) return;
    int d = gid & 511;
    int bs = gid >> 9;
    int seg = bs & (SEG - 1);
    int b = bs / SEG;
    size_t base = (size_t)b * TD * DD + (size_t)seg * SEGLEN * DD + d;
    float hc = g_scanH[gid];
#pragma unroll 8
    for (int t = 0; t < SEGLEN; ++t) {
        size_t idx = base + (size_t)t * DD;
        float zv = 1.0f / (1.0f + expf(-zl[idx]));
        hc = fmaf(zv, hb[idx] - hc, hc);
        h[idx] = hc;
    }
}

// ---------------------------------------------------------------------------
// Max-abs norm, in place
// ---------------------------------------------------------------------------
__global__ __launch_bounds__(256) void norm_kernel(float* __restrict__ h, int rows) {
    int warp = (blockIdx.x * blockDim.x + threadIdx.x) >> 5;
    int lane = threadIdx.x & 31;
    if (warp >= rows) return;
    float4* row = (float4*)(h + (size_t)warp * DD);
    float4 vals[4];
    float m = 0.0f;
#pragma unroll
    for (int j = 0; j < 4; ++j) {
        vals[j] = row[lane + 32 * j];
        m = fmaxf(m, fmaxf(fmaxf(fabsf(vals[j].x), fabsf(vals[j].y)),
                           fmaxf(fabsf(vals[j].z), fabsf(vals[j].w))));
    }
#pragma unroll
    for (int off = 16; off; off >>= 1)
        m = fmaxf(m, __shfl_xor_sync(0xffffffffu, m, off));
    float inv = 1.0f / (m + 1e-6f);
#pragma unroll
    for (int j = 0; j < 4; ++j) {
        vals[j].x *= inv; vals[j].y *= inv; vals[j].z *= inv; vals[j].w *= inv;
        row[lane + 32 * j] = vals[j];
    }
}

// ---------------------------------------------------------------------------
// kernel_launch (launch #3 = paired apl_hmma for the ncu capture window)
// ---------------------------------------------------------------------------
extern "C" void kernel_launch(void* const* d_in, const int* in_sizes, int n_in,
                              void* d_out, int out_size) {
    const float* x   = (const float*)d_in[0];
    const float* pz0 = (const float*)d_in[1];
    const float* vz0 = (const float*)d_in[2];
    const float* ph0 = (const float*)d_in[3];
    const float* vh0 = (const float*)d_in[4];
    const float* pz1 = (const float*)d_in[5];
    const float* vz1 = (const float*)d_in[6];
    const float* ph1 = (const float*)d_in[7];
    const float* vh1 = (const float*)d_in[8];
    const float* po  = (const float*)d_in[9];
    const float* vo  = (const float*)d_in[10];

    const int N = in_sizes[0] / DD;  // 16384

    float *s0, *s1, *zl, *hb;
    __half *bhi;
    cudaGetSymbolAddress((void**)&s0, g_s0);
    cudaGetSymbolAddress((void**)&s1, g_s1);
    cudaGetSymbolAddress((void**)&zl, g_zl);
    cudaGetSymbolAddress((void**)&hb, g_hbar);
    cudaGetSymbolAddress((void**)&bhi, g_bt_hi);

    static int smem_set = 0;
    if (!smem_set) {
        cudaFuncSetAttribute(apl_hmma_kernel,
                             cudaFuncAttributeMaxDynamicSharedMemorySize, SMEM_REQ);
        smem_set = 1;
    }

    float* out = (float*)d_out;
    float* h1  = out + (size_t)N * DD;
    float* h2  = h1 + (size_t)N * DD;

    dim3 tgrid(DD / 32, N / 32, 2);
    dim3 tblk(32, 8);
    dim3 spgrid(64, 4, 5);
    dim3 gpair(N / 128, DD / 128, 2);
    dim3 gone(N / 128, DD / 128, 1);
    const int p1_blocks = (BD * SEG * DD + 255) / 256;
    const int p2_blocks = (BD * DD + 255) / 256;
    const int norm_blocks = (N * 32 + 255) / 256;
    const size_t LSZ = (size_t)4 * 64 * 8192;

    // [1] pre-stage all V into chunked/pre-swizzled fp16 tiles
    split_chunk_kernel<<<spgrid, 256>>>(vz0, vh0, vz1, vh1, vo);

    // ---- layer 0 ----
    build_s_pair_kernel<<<tgrid, tblk>>>(x, pz0, ph0, s0, s1, N);            // [2]
    apl_hmma_kernel<<<gpair, 256, SMEM_REQ>>>(s0, s1, bhi + 0 * LSZ,
                                              bhi + 1 * LSZ, zl, hb);        // [3] profiled
    scan_p1<<<p1_blocks, 256>>>(zl, hb);
    scan_p2<<<p2_blocks, 256>>>();
    scan_p3<<<p1_blocks, 256>>>(zl, hb, h1);
    norm_kernel<<<norm_blocks, 256>>>(h1, N);

    // ---- layer 1 ----
    build_s_pair_kernel<<<tgrid, tblk>>>(h1, pz1, ph1, s0, s1, N);
    apl_hmma_kernel<<<gpair, 256, SMEM_REQ>>>(s0, s1, bhi + 2 * LSZ,
                                              bhi + 3 * LSZ, zl, hb);
    scan_p1<<<p1_blocks, 256>>>(zl, hb);
    scan_p2<<<p2_blocks, 256>>>();
    scan_p3<<<p1_blocks, 256>>>(zl, hb, h2);
    norm_kernel<<<norm_blocks, 256>>>(h2, N);

    // ---- output APL ----
    build_s_pair_kernel<<<dim3(DD / 32, N / 32, 1), tblk>>>(h2, po, po, s0, s1, N);
    apl_hmma_kernel<<<gone, 256, SMEM_REQ>>>(s0, s0, bhi + 4 * LSZ,
                                             bhi + 4 * LSZ, out, out);
}

// round 10
// speedup vs baseline: 8.5419x; 1.0665x over previous
#include <cuda_runtime.h>
#include <cuda_fp16.h>
#include <math.h>
#include <stdint.h>

// Problem constants
#define BD   8
#define TD   2048
#define DD   512
#define NTOT (BD * TD)     // 16384
#define KTOT 4096          // D * P
#define NKC  64            // K-chunks of 64 elements
#define SEG  64
#define SEGLEN (TD / SEG)  // 32

// ---------------------------------------------------------------------------
// Scratch (device globals — no allocations allowed)
// ---------------------------------------------------------------------------
__device__ float g_s0[(size_t)DD * NTOT];
__device__ float g_s1[(size_t)DD * NTOT];
__device__ float g_zl[(size_t)NTOT * DD];
__device__ float g_hbar[(size_t)NTOT * DD];
// Pre-swizzled chunk tiles: [layer][nb(4)][kc(64)] each 16KB (128 rows x 64 cols fp16)
__device__ __half g_bt_hi[5][(size_t)4 * 64 * 8192];
// scan scratch
__device__ float g_scanA[BD * SEG * DD];
__device__ float g_scanB[BD * SEG * DD];
__device__ float g_scanH[BD * SEG * DD];

// ---------------------------------------------------------------------------
// helpers
// ---------------------------------------------------------------------------
__device__ __forceinline__ uint32_t smem_u32(const void* p) {
    uint32_t a;
    asm("{ .reg .u64 t; cvta.to.shared.u64 t, %1; cvt.u32.u64 %0, t; }"
        : "=r"(a) : "l"(p));
    return a;
}

#define SWZ(x) ((x) ^ (((x) >> 3) & 0x70))

__device__ __forceinline__ void mbar_init(uint32_t a, uint32_t cnt) {
    asm volatile("mbarrier.init.shared.b64 [%0], %1;" :: "r"(a), "r"(cnt) : "memory");
}

__device__ __forceinline__ void mbar_wait(uint32_t a, uint32_t ph) {
    asm volatile(
        "{\n\t.reg .pred P;\n\t"
        "W%=:\n\t"
        "mbarrier.try_wait.parity.acquire.cta.shared::cta.b64 P, [%0], %1, 0x989680;\n\t"
        "@P bra.uni D%=;\n\t"
        "bra.uni W%=;\n\t"
        "D%=:\n\t}"
        :: "r"(a), "r"(ph) : "memory");
}

__device__ __forceinline__ void mbar_expect_tx(uint32_t a, uint32_t bytes) {
    asm volatile("mbarrier.arrive.expect_tx.shared.b64 _, [%0], %1;"
                 :: "r"(a), "r"(bytes) : "memory");
}

__device__ __forceinline__ void bulk_ld(uint32_t dst, const void* src,
                                        uint32_t bytes, uint32_t mbar) {
    asm volatile(
        "cp.async.bulk.shared::cluster.global.mbarrier::complete_tx::bytes "
        "[%0], [%1], %2, [%3];"
        :: "r"(dst), "l"(src), "r"(bytes), "r"(mbar) : "memory");
}

// ---------------------------------------------------------------------------
// build_s (paired via blockIdx.z): s[i*N+n] = k + t
// ---------------------------------------------------------------------------
__global__ __launch_bounds__(256) void build_s_pair_kernel(
    const float* __restrict__ X, const float* __restrict__ P0,
    const float* __restrict__ P1, float* __restrict__ S0,
    float* __restrict__ S1, int N) {
    const float* Pp = blockIdx.z ? P1 : P0;
    float* S = blockIdx.z ? S1 : S0;
    __shared__ float tile[32][33];
    int i0 = blockIdx.x * 32;
    int n0 = blockIdx.y * 32;
    int tx = threadIdx.x;
    int ty = threadIdx.y;
    int i = i0 + tx;

    float p[8];
#pragma unroll
    for (int j = 0; j < 8; ++j) p[j] = Pp[i * 8 + j];

#pragma unroll
    for (int r = 0; r < 4; ++r) {
        int nl = ty + 8 * r;
        int n = n0 + nl;
        float x = X[(size_t)n * DD + i];
        int k = 0;
        float pl = p[0], pr = p[1];
#pragma unroll
        for (int j = 1; j <= 6; ++j) {
            if (p[j] < x) { k = j; pl = p[j]; pr = p[j + 1]; }
        }
        float t = (x - pl) / (pr - pl);
        t = fminf(fmaxf(t, 0.0f), 1.0f);
        tile[nl][tx] = (float)k + t;
    }
    __syncthreads();
#pragma unroll
    for (int r = 0; r < 4; ++r) {
        int il = ty + 8 * r;
        S[(size_t)(i0 + il) * N + n0 + tx] = tile[tx][il];
    }
}

// ---------------------------------------------------------------------------
// split_chunk: v (4096 x 512 f32) -> pre-swizzled 16KB chunk tiles, fp16.
// grid (64 kc, 4 nb, nlayers); layer index = ibase + blockIdx.z
// ---------------------------------------------------------------------------
__global__ __launch_bounds__(256) void split_chunk_kernel(
    const float* __restrict__ va, const float* __restrict__ vb,
    const float* __restrict__ vc, int ibase) {
    int kc = blockIdx.x, nb = blockIdx.y, z = blockIdx.z;
    const float* v = (z == 0) ? va : (z == 1) ? vb : vc;
    int layer = ibase + z;
    size_t tile_off = ((size_t)layer * 256 + nb * 64 + kc) << 14;  // bytes
    char* hib = (char*)g_bt_hi + tile_off;

    int r = threadIdx.x & 127;
    int chalf = threadIdx.x >> 7;
#pragma unroll
    for (int j = 0; j < 32; ++j) {
        int c = chalf * 32 + j;
        float val = v[(size_t)(kc * 64 + c) * DD + nb * 128 + r];
        uint32_t off = SWZ((uint32_t)(r * 128 + c * 2));
        *(__half*)(hib + off) = __float2half_rn(val);
    }
}

// ---------------------------------------------------------------------------
// APL HMMA GEMM, single fp16 term, B via cp.async.bulk (4-stage ring).
// 256 threads, 8 warps (2Mx4N), warp tile 64x32, CTA tile 128x128, 2 CTA/SM.
// S prefetched into registers two chunks ahead.
// ---------------------------------------------------------------------------
#define TILE16K 16384
#define SMEM_REQ (1024 + 2 * TILE16K + 4 * TILE16K)

__device__ __forceinline__ void load_S4(const float* __restrict__ S, int bm,
                                        int kc, int tid, float* sv) {
#pragma unroll
    for (int q = 0; q < 4; ++q) {
        int idx = tid + 256 * q;
        int n = idx & 127;
        int il = idx >> 7;
        sv[q] = __ldg(&S[(size_t)(kc * 8 + il) * NTOT + bm + n]);
    }
}

__device__ __forceinline__ void build_A_store(const float* sv, uint32_t ahi,
                                              int tid) {
#pragma unroll
    for (int q = 0; q < 4; ++q) {
        int idx = tid + 256 * q;
        int n = idx & 127;
        int il = idx >> 7;
        float svv = sv[q];
        int k = min((int)svv, 6);
        float t = svv - (float)k;
        __half2 h2 = __floats2half2_rn(1.0f - t, t);
        uint32_t Phi = *(uint32_t*)&h2;
        int j = k >> 1;
        int odd = k & 1;
        uint32_t e = odd ? (Phi << 16) : Phi;
        uint32_t sft = odd ? (Phi >> 16) : 0u;
        uint32_t w[4];
#pragma unroll
        for (int m = 0; m < 4; ++m)
            w[m] = (m == j) ? e : ((m == j + 1) ? sft : 0u);
        uint32_t off = SWZ((uint32_t)(n * 128 + il * 16));
        asm volatile("st.shared.v4.b32 [%0], {%1,%2,%3,%4};"
                     :: "r"(ahi + off), "r"(w[0]), "r"(w[1]), "r"(w[2]), "r"(w[3])
                     : "memory");
    }
}

__device__ __forceinline__ void ldsm4(uint32_t a, uint32_t& r0, uint32_t& r1,
                                      uint32_t& r2, uint32_t& r3) {
    asm volatile("ldmatrix.sync.aligned.m8n8.x4.shared.b16 {%0,%1,%2,%3}, [%4];"
                 : "=r"(r0), "=r"(r1), "=r"(r2), "=r"(r3) : "r"(a));
}

__device__ __forceinline__ void mma16816(float* d, const uint32_t* a,
                                         const uint32_t* b) {
    asm volatile(
        "mma.sync.aligned.m16n8k16.row.col.f32.f16.f16.f32 "
        "{%0,%1,%2,%3}, {%4,%5,%6,%7}, {%8,%9}, {%0,%1,%2,%3};"
        : "+f"(d[0]), "+f"(d[1]), "+f"(d[2]), "+f"(d[3])
        : "r"(a[0]), "r"(a[1]), "r"(a[2]), "r"(a[3]), "r"(b[0]), "r"(b[1]));
}

__global__ void __launch_bounds__(256, 2) apl_hmma_kernel(
    const float* __restrict__ S0, const float* __restrict__ S1,
    const __half* __restrict__ Bhi0, const __half* __restrict__ Bhi1,
    float* __restrict__ out0, float* __restrict__ out1) {
    const int zz = blockIdx.z;
    const float* S = zz ? S1 : S0;
    const __half* Bhi = zz ? Bhi1 : Bhi0;
    float* out = zz ? out1 : out0;

    extern __shared__ char smem[];
    uint32_t sb = (smem_u32(smem) + 1023u) & ~1023u;
    const uint32_t MB = sb;                  // 4 mbarriers @ +0,8,16,24
    const uint32_t AH = sb + 1024;           // 2 x 16KB
    const uint32_t BH = AH + 2 * TILE16K;    // 4 x 16KB
    const int tid = threadIdx.x;
    const int lane = tid & 31;
    const int wid = tid >> 5;
    const int wm = wid & 1;             // 2 warp rows (64 each)
    const int wn = wid >> 1;            // 4 warp cols (32 each)
    const int bm = blockIdx.x * 128;
    const int nb = blockIdx.y;

    const char* hsrc = (const char*)Bhi + ((size_t)nb * 64 << 14);

    if (tid == 0) {
        mbar_init(MB + 0, 1);
        mbar_init(MB + 8, 1);
        mbar_init(MB + 16, 1);
        mbar_init(MB + 24, 1);
        asm volatile("fence.proxy.async.shared::cta;" ::: "memory");
    }
    __syncthreads();

    float acc[4][4][4];
#pragma unroll
    for (int mi = 0; mi < 4; ++mi)
#pragma unroll
        for (int nj = 0; nj < 4; ++nj)
#pragma unroll
            for (int u = 0; u < 4; ++u) acc[mi][nj][u] = 0.0f;

    uint32_t a_off[4], b_off[2];
#pragma unroll
    for (int mi = 0; mi < 4; ++mi) {
        int row = wm * 64 + mi * 16 + (lane & 15);
        a_off[mi] = (uint32_t)(row * 128 + (lane >> 4) * 16);
    }
#pragma unroll
    for (int ni = 0; ni < 2; ++ni) {
        int row = wn * 32 + ni * 16 + (lane & 7) + ((lane & 16) >> 1);
        b_off[ni] = (uint32_t)(row * 128 + ((lane >> 3) & 1) * 16);
    }

    // prologue: B chunks 0..2 in flight; A(0) built; S(1) in regs
    if (tid == 0) {
#pragma unroll
        for (int c = 0; c < 3; ++c) {
            mbar_expect_tx(MB + c * 8, TILE16K);
            bulk_ld(BH + c * TILE16K, hsrc + ((size_t)c << 14), TILE16K, MB + c * 8);
        }
    }
    float sv_cur[4], sv_nxt[4];
    load_S4(S, bm, 0, tid, sv_cur);
    build_A_store(sv_cur, AH, tid);
    load_S4(S, bm, 1, tid, sv_nxt);

    for (int kc = 0; kc < NKC; ++kc) {
        int st = kc & 3;
        uint32_t parity = (uint32_t)((kc >> 2) & 1);
        mbar_wait(MB + st * 8, parity);
        __syncthreads();   // B(kc) ready; A(kc) built; stage (kc+3)&3 free

        if (tid == 0 && kc + 3 < NKC) {
            int s2 = (kc + 3) & 3;
            mbar_expect_tx(MB + s2 * 8, TILE16K);
            bulk_ld(BH + s2 * TILE16K, hsrc + ((size_t)(kc + 3) << 14), TILE16K,
                    MB + s2 * 8);
        }

        const uint32_t AHc = AH + (kc & 1) * TILE16K;
        const uint32_t BHc = BH + st * TILE16K;

#pragma unroll
        for (int kk = 0; kk < 4; ++kk) {
            uint32_t ah[4][4], bh[4][2];
#pragma unroll
            for (int mi = 0; mi < 4; ++mi)
                ldsm4(AHc + SWZ(a_off[mi] + kk * 32),
                      ah[mi][0], ah[mi][1], ah[mi][2], ah[mi][3]);
#pragma unroll
            for (int ni = 0; ni < 2; ++ni) {
                uint32_t r0, r1, r2, r3;
                ldsm4(BHc + SWZ(b_off[ni] + kk * 32), r0, r1, r2, r3);
                bh[2 * ni][0] = r0; bh[2 * ni][1] = r1;
                bh[2 * ni + 1][0] = r2; bh[2 * ni + 1][1] = r3;
            }
#pragma unroll
            for (int mi = 0; mi < 4; ++mi)
#pragma unroll
                for (int nj = 0; nj < 4; ++nj)
                    mma16816(acc[mi][nj], ah[mi], bh[nj]);
        }

        // build A(kc+1) from prefetched regs, then prefetch S(kc+2)
        if (kc + 1 < NKC) {
            build_A_store(sv_nxt, AH + ((kc + 1) & 1) * TILE16K, tid);
            if (kc + 2 < NKC)
                load_S4(S, bm, kc + 2, tid, sv_nxt);
        }
    }

    // epilogue
#pragma unroll
    for (int mi = 0; mi < 4; ++mi) {
#pragma unroll
        for (int nj = 0; nj < 4; ++nj) {
            int row = bm + wm * 64 + mi * 16 + (lane >> 2);
            int col = nb * 128 + wn * 32 + nj * 8 + 2 * (lane & 3);
            float2* p0 = (float2*)&out[(size_t)row * DD + col];
            float2* p1 = (float2*)&out[(size_t)(row + 8) * DD + col];
            *p0 = make_float2(acc[mi][nj][0], acc[mi][nj][1]);
            *p1 = make_float2(acc[mi][nj][2], acc[mi][nj][3]);
        }
    }
}

// ---------------------------------------------------------------------------
// Segmented scan, SEG=64. p1: per-segment (A,B); p2: segment states;
// p3+norm fused: final recurrence + per-(b,t) maxabs normalization.
// ---------------------------------------------------------------------------
__global__ __launch_bounds__(256) void scan_p1(
    const float* __restrict__ zl, const float* __restrict__ hb) {
    int gid = blockIdx.x * blockDim.x + threadIdx.x;
    if (gid >= BD * SEG * DD) return;
    int d = gid & 511;
    int bs = gid >> 9;
    int seg = bs & (SEG - 1);
    int b = bs / SEG;
    size_t base = (size_t)b * TD * DD + (size_t)seg * SEGLEN * DD + d;
    float A = 1.0f, Bv = 0.0f;
#pragma unroll 8
    for (int t = 0; t < SEGLEN; ++t) {
        size_t idx = base + (size_t)t * DD;
        float zv = 1.0f / (1.0f + expf(-zl[idx]));
        float a = 1.0f - zv;
        float bb = zv * hb[idx];
        A *= a;
        Bv = fmaf(a, Bv, bb);
    }
    g_scanA[gid] = A;
    g_scanB[gid] = Bv;
}

__global__ __launch_bounds__(256) void scan_p2() {
    int c = blockIdx.x * blockDim.x + threadIdx.x;
    if (c >= BD * DD) return;
    int d = c & 511;
    int b = c >> 9;
    float h = 0.0f;
#pragma unroll
    for (int seg = 0; seg < SEG; ++seg) {
        int gid = ((b * SEG + seg) << 9) + d;
        g_scanH[gid] = h;
        h = fmaf(g_scanA[gid], h, g_scanB[gid]);
    }
}

// block = 512 threads (all d of one (b,seg)); fused maxabs norm per t-row.
__global__ __launch_bounds__(512) void scan_p3_norm(
    const float* __restrict__ zl, const float* __restrict__ hb,
    float* __restrict__ h) {
    __shared__ float red[34];   // two banks of 17 (double-buffered by t parity)
    int blk = blockIdx.x;       // b*SEG + seg
    int d = threadIdx.x;
    int seg = blk & (SEG - 1);
    int b = blk / SEG;
    int lane = d & 31, wid = d >> 5;
    size_t base = (size_t)b * TD * DD + (size_t)seg * SEGLEN * DD + d;
    float hc = g_scanH[(blk << 9) + d];

    for (int t = 0; t < SEGLEN; ++t) {
        size_t idx = base + (size_t)t * DD;
        float zv = 1.0f / (1.0f + expf(-zl[idx]));
        hc = fmaf(zv, hb[idx] - hc, hc);   // raw recurrence state
        int slot = (t & 1) * 17;
        float m = fabsf(hc);
#pragma unroll
        for (int o = 16; o; o >>= 1)
            m = fmaxf(m, __shfl_xor_sync(0xffffffffu, m, o));
        if (lane == 0) red[slot + wid] = m;
        __syncthreads();
        if (wid == 0) {
            float mm = red[slot + (lane & 15)];
#pragma unroll
            for (int o = 8; o; o >>= 1)
                mm = fmaxf(mm, __shfl_xor_sync(0xffffffffu, mm, o));
            if (lane == 0) red[slot + 16] = mm;
        }
        __syncthreads();
        float inv = 1.0f / (red[slot + 16] + 1e-6f);
        h[idx] = hc * inv;                 // normalized output
    }
}

// ---------------------------------------------------------------------------
// kernel_launch (launch #4 = paired apl_hmma for the ncu capture window)
// ---------------------------------------------------------------------------
extern "C" void kernel_launch(void* const* d_in, const int* in_sizes, int n_in,
                              void* d_out, int out_size) {
    const float* x   = (const float*)d_in[0];
    const float* pz0 = (const float*)d_in[1];
    const float* vz0 = (const float*)d_in[2];
    const float* ph0 = (const float*)d_in[3];
    const float* vh0 = (const float*)d_in[4];
    const float* pz1 = (const float*)d_in[5];
    const float* vz1 = (const float*)d_in[6];
    const float* ph1 = (const float*)d_in[7];
    const float* vh1 = (const float*)d_in[8];
    const float* po  = (const float*)d_in[9];
    const float* vo  = (const float*)d_in[10];

    const int N = in_sizes[0] / DD;  // 16384

    float *s0, *s1, *zl, *hb;
    __half *bhi;
    cudaGetSymbolAddress((void**)&s0, g_s0);
    cudaGetSymbolAddress((void**)&s1, g_s1);
    cudaGetSymbolAddress((void**)&zl, g_zl);
    cudaGetSymbolAddress((void**)&hb, g_hbar);
    cudaGetSymbolAddress((void**)&bhi, g_bt_hi);

    static int smem_set = 0;
    if (!smem_set) {
        cudaFuncSetAttribute(apl_hmma_kernel,
                             cudaFuncAttributeMaxDynamicSharedMemorySize, SMEM_REQ);
        smem_set = 1;
    }

    float* out = (float*)d_out;
    float* h1  = out + (size_t)N * DD;
    float* h2  = h1 + (size_t)N * DD;

    dim3 tgrid(DD / 32, N / 32, 2);
    dim3 tblk(32, 8);
    dim3 sp3(64, 4, 3);
    dim3 sp2(64, 4, 2);
    dim3 gpair(N / 128, DD / 128, 2);
    dim3 gone(N / 128, DD / 128, 1);
    const int p1_blocks = (BD * SEG * DD + 255) / 256;
    const int p2_blocks = (BD * DD + 255) / 256;
    const int p3_blocks = BD * SEG;
    const size_t LSZ = (size_t)4 * 64 * 8192;

    // [1][2] pre-stage all V into chunked/pre-swizzled fp16 tiles
    split_chunk_kernel<<<sp3, 256>>>(vz0, vh0, vz1, 0);
    split_chunk_kernel<<<sp2, 256>>>(vh1, vo, vo, 3);

    // ---- layer 0 ----
    build_s_pair_kernel<<<tgrid, tblk>>>(x, pz0, ph0, s0, s1, N);            // [3]
    apl_hmma_kernel<<<gpair, 256, SMEM_REQ>>>(s0, s1, bhi + 0 * LSZ,
                                              bhi + 1 * LSZ, zl, hb);        // [4] profiled
    scan_p1<<<p1_blocks, 256>>>(zl, hb);
    scan_p2<<<p2_blocks, 256>>>();
    scan_p3_norm<<<p3_blocks, 512>>>(zl, hb, h1);

    // ---- layer 1 ----
    build_s_pair_kernel<<<tgrid, tblk>>>(h1, pz1, ph1, s0, s1, N);
    apl_hmma_kernel<<<gpair, 256, SMEM_REQ>>>(s0, s1, bhi + 2 * LSZ,
                                              bhi + 3 * LSZ, zl, hb);
    scan_p1<<<p1_blocks, 256>>>(zl, hb);
    scan_p2<<<p2_blocks, 256>>>();
    scan_p3_norm<<<p3_blocks, 512>>>(zl, hb, h2);

    // ---- output APL ----
    build_s_pair_kernel<<<dim3(DD / 32, N / 32, 1), tblk>>>(h2, po, po, s0, s1, N);
    apl_hmma_kernel<<<gone, 256, SMEM_REQ>>>(s0, s0, bhi + 4 * LSZ,
                                             bhi + 4 * LSZ, out, out);
}